// round 10
// baseline (speedup 1.0000x reference)
#include <cuda_runtime.h>
#include <cuda_fp16.h>
#include <cstdint>

// Problem constants
constexpr int Qn = 4096, Cn = 4096, Dn = 1024;
#define EPSV 1e-6f

// GEMM config: CTA 128(M) x 64(N), KC=32 halfs, 3-stage cp.async, 256 threads
// 8 warps as 4(m) x 2(n); warp tile 32x32. Occupancy 2.
constexpr int BM = 128, BN = 64, KC = 32;
constexpr int NK = Dn / KC;                 // 32
constexpr int STAGES = 3;
constexpr int RSTRIDE = 80;                 // bytes per 32-half row (64B data + 16B pad)
constexpr int MOD_A = 128 * RSTRIDE;        // 10240
constexpr int MOD_B = 64 * RSTRIDE;         // 5120
constexpr int BOFF = 2 * MOD_A;             // 20480
constexpr int STAGE_BYTES = 2 * MOD_A + 2 * MOD_B;  // 30720
constexpr int SMEM_TOTAL = STAGES * STAGE_BYTES;    // 92160 (x2 CTAs = 184320)
constexpr int NCTA_C = Cn / BN;             // 64 column tiles
constexpr int NPSUM = 2 * NCTA_C;           // 128 partials per row

// Scratch (static __device__ — no cudaMalloc allowed)
__device__ __half g_h[4][(size_t)Qn * Dn];  // 0=c_rgb 1=c_flow 2=t_rgb(+eps) 3=t_flow(+eps)
__device__ float g_nt[2][Qn];
__device__ float g_nc[2][Cn];
__device__ float g_psum[NPSUM][Qn];         // per-(colTile,warp-half) row partial sums

// ---------------------------------------------------------------------------
// helpers
// ---------------------------------------------------------------------------
__device__ __forceinline__ uint32_t smem_u32(const void* p) {
    uint32_t a;
    asm("{ .reg .u64 t; cvta.to.shared.u64 t, %1; cvt.u32.u64 %0, t; }"
        : "=r"(a) : "l"(p));
    return a;
}
__device__ __forceinline__ void cp16(uint32_t saddr, const void* g) {
    asm volatile(
        "{ .reg .u64 gg; cvta.to.global.u64 gg, %1; "
        "cp.async.cg.shared.global [%0], [gg], 16; }"
        :: "r"(saddr), "l"(g));
}
__device__ __forceinline__ float sqrt_ap(float x) {
    float r; asm("sqrt.approx.f32 %0, %1;" : "=f"(r) : "f"(x)); return r;
}
#define LDSM_X4(r0, r1, r2, r3, addr) \
    asm volatile("ldmatrix.sync.aligned.m8n8.x4.shared.b16 {%0,%1,%2,%3}, [%4];" \
        : "=r"(r0), "=r"(r1), "=r"(r2), "=r"(r3) : "r"(addr))
#define MMA16816(d, a, b) \
    asm volatile( \
        "mma.sync.aligned.m16n8k16.row.col.f32.f16.f16.f32 " \
        "{%0,%1,%2,%3}, {%4,%5,%6,%7}, {%8,%9}, {%0,%1,%2,%3};" \
        : "+f"((d)[0]), "+f"((d)[1]), "+f"((d)[2]), "+f"((d)[3]) \
        : "r"((a)[0]), "r"((a)[1]), "r"((a)[2]), "r"((a)[3]), \
          "r"((b)[0]), "r"((b)[1]))

// ---------------------------------------------------------------------------
// Kernel 1: convert f32 -> f16 (rn, targets +eps first) + fp32 row norms
// ---------------------------------------------------------------------------
__global__ __launch_bounds__(128) void prep_kernel(
    const float* __restrict__ t_rgb, const float* __restrict__ t_flow,
    const float* __restrict__ c_rgb, const float* __restrict__ c_flow)
{
    int b = blockIdx.x;
    const float* src; float* dstN; __half* dstH; float eps;
    if (b < Qn)               { src = t_rgb  + (size_t)b * Dn;                 dstN = &g_nt[0][b];               dstH = g_h[2] + (size_t)b * Dn;                 eps = EPSV; }
    else if (b < 2 * Qn)      { src = t_flow + (size_t)(b - Qn) * Dn;          dstN = &g_nt[1][b - Qn];          dstH = g_h[3] + (size_t)(b - Qn) * Dn;          eps = EPSV; }
    else if (b < 2 * Qn + Cn) { src = c_rgb  + (size_t)(b - 2 * Qn) * Dn;      dstN = &g_nc[0][b - 2 * Qn];      dstH = g_h[0] + (size_t)(b - 2 * Qn) * Dn;      eps = 0.0f; }
    else                      { src = c_flow + (size_t)(b - 2 * Qn - Cn) * Dn; dstN = &g_nc[1][b - 2 * Qn - Cn]; dstH = g_h[1] + (size_t)(b - 2 * Qn - Cn) * Dn; eps = 0.0f; }

    float4 v0 = reinterpret_cast<const float4*>(src)[threadIdx.x];
    float4 v1 = reinterpret_cast<const float4*>(src)[threadIdx.x + 128];
    v0.x += eps; v0.y += eps; v0.z += eps; v0.w += eps;
    v1.x += eps; v1.y += eps; v1.z += eps; v1.w += eps;

    __half2* hp0 = reinterpret_cast<__half2*>(dstH) + threadIdx.x * 2;
    hp0[0] = __floats2half2_rn(v0.x, v0.y);
    hp0[1] = __floats2half2_rn(v0.z, v0.w);
    __half2* hp1 = reinterpret_cast<__half2*>(dstH) + (threadIdx.x + 128) * 2;
    hp1[0] = __floats2half2_rn(v1.x, v1.y);
    hp1[1] = __floats2half2_rn(v1.z, v1.w);

    float s = v0.x * v0.x + v0.y * v0.y + v0.z * v0.z + v0.w * v0.w
            + v1.x * v1.x + v1.y * v1.y + v1.z * v1.z + v1.w * v1.w;
    __shared__ float red[4];
    #pragma unroll
    for (int o = 16; o > 0; o >>= 1) s += __shfl_xor_sync(0xffffffffu, s, o);
    if ((threadIdx.x & 31) == 0) red[threadIdx.x >> 5] = s;
    __syncthreads();
    if (threadIdx.x < 4) {
        s = red[threadIdx.x];
        #pragma unroll
        for (int o = 2; o > 0; o >>= 1) s += __shfl_xor_sync(0xfu, s, o);
        if (threadIdx.x == 0) *dstN = s;
    }
}

// ---------------------------------------------------------------------------
// Kernel 2: dual f16 mma GEMM (128x64 CTA, 8 warps 4x2, 32x32 warp tile)
//           + fused distance/exp/mix epilogue + per-row partial sums
// ---------------------------------------------------------------------------
__global__ __launch_bounds__(256, 2) void fused_mma_kernel(
    const float* __restrict__ crP, const float* __restrict__ cfP,
    float* __restrict__ out)
{
    extern __shared__ char smem[];
    const uint32_t sb = smem_u32(smem);
    const int tid = threadIdx.x, wid = tid >> 5, l = tid & 31;
    const int wm = wid & 3, wn = wid >> 2;
    const int q0 = blockIdx.y * BM, c0 = blockIdx.x * BN;

    // --- loader mapping: 6 x 16B chunks per thread per stage ---
    const __half* gSrc[6]; uint32_t sDst[6];
    #pragma unroll
    for (int it = 0; it < 6; ++it) {
        const int id = tid + it * 256;            // 0..1535
        if (id < 1024) {
            const int mod = id >> 9, rem = id & 511;
            const int row = rem >> 2, c16 = rem & 3;
            gSrc[it] = g_h[2 + mod] + (size_t)(q0 + row) * Dn + c16 * 8;
            sDst[it] = (uint32_t)(mod * MOD_A + row * RSTRIDE + c16 * 16);
        } else {
            const int id2 = id - 1024;
            const int mod = id2 >> 8, rem = id2 & 255;
            const int row = rem >> 2, c16 = rem & 3;
            gSrc[it] = g_h[mod] + (size_t)(c0 + row) * Dn + c16 * 8;
            sDst[it] = (uint32_t)(BOFF + mod * MOD_B + row * RSTRIDE + c16 * 16);
        }
    }
    auto issue_stage = [&](int kc) {
        const uint32_t stg = sb + (uint32_t)(kc % STAGES) * STAGE_BYTES;
        const int ko = kc * KC;
        #pragma unroll
        for (int it = 0; it < 6; ++it)
            cp16(stg + sDst[it], gSrc[it] + ko);
        asm volatile("cp.async.commit_group;" ::: "memory");
    };

    // --- ldmatrix lane offsets (80B padded rows -> conflict-free) ---
    const uint32_t aOff = (uint32_t)(((l & 7) + ((l >> 3) & 1) * 8) * RSTRIDE
                                     + ((l >> 4) & 1) * 16);
    const uint32_t bOff4 = (uint32_t)(((l & 7) + ((l >> 4) & 1) * 8) * RSTRIDE
                                      + ((l >> 3) & 1) * 16);
    const uint32_t aBase = (uint32_t)(wm * 32 * RSTRIDE);
    const uint32_t bBase = (uint32_t)(BOFF + wn * 32 * RSTRIDE);

    float acc[2][2][4][4];   // [mod][m-frag(16)][n-frag(8)][e]
    #pragma unroll
    for (int m = 0; m < 2; ++m)
        #pragma unroll
        for (int i = 0; i < 2; ++i)
            #pragma unroll
            for (int j = 0; j < 4; ++j)
                #pragma unroll
                for (int e = 0; e < 4; ++e) acc[m][i][j][e] = 0.0f;

    issue_stage(0); issue_stage(1);

    for (int kc = 0; kc < NK; ++kc) {
        if (kc < NK - 1) asm volatile("cp.async.wait_group 1;" ::: "memory");
        else             asm volatile("cp.async.wait_group 0;" ::: "memory");
        __syncthreads();
        if (kc + 2 < NK) issue_stage(kc + 2);

        const uint32_t stg = sb + (uint32_t)(kc % STAGES) * STAGE_BYTES;
        #pragma unroll
        for (int s = 0; s < 2; ++s) {             // two k16 steps per KC=32
            #pragma unroll
            for (int m = 0; m < 2; ++m) {         // modality
                const uint32_t Am = stg + (uint32_t)(m * MOD_A) + aBase + s * 32 + aOff;
                const uint32_t Bm = stg + (uint32_t)(m * MOD_B) + bBase + s * 32 + bOff4;
                uint32_t a[2][4], b8[4][2];
                LDSM_X4(a[0][0], a[0][1], a[0][2], a[0][3], Am);
                LDSM_X4(a[1][0], a[1][1], a[1][2], a[1][3], Am + 16 * RSTRIDE);
                LDSM_X4(b8[0][0], b8[0][1], b8[1][0], b8[1][1], Bm);
                LDSM_X4(b8[2][0], b8[2][1], b8[3][0], b8[3][1], Bm + 16 * RSTRIDE);
                #pragma unroll
                for (int i = 0; i < 2; ++i)
                    #pragma unroll
                    for (int j = 0; j < 4; ++j)
                        MMA16816(acc[m][i][j], a[i], b8[j]);
            }
        }
    }

    // --- fused epilogue (+ deterministic per-row partial sums) ---
    const int r = l >> 2, cq = l & 3;
    const int psIdx = blockIdx.x * 2 + wn;
    #pragma unroll
    for (int i = 0; i < 2; ++i) {
        #pragma unroll
        for (int h = 0; h < 2; ++h) {
            const int q = q0 + wm * 32 + i * 16 + r + h * 8;
            const float ntR = g_nt[0][q], ntF = g_nt[1][q];
            const float rr = __ldg(crP + q), ff = __ldg(cfP + q);
            const float inv = 1.0f / (rr + ff);
            const float wr = rr * inv, wf = ff * inv;
            float rs = 0.0f;
            #pragma unroll
            for (int j = 0; j < 4; ++j) {
                const int c = c0 + wn * 32 + j * 8 + 2 * cq;
                float o[2];
                #pragma unroll
                for (int ec = 0; ec < 2; ++ec) {
                    const float sR = ntR + g_nc[0][c + ec] - 2.0f * acc[0][i][j][h * 2 + ec];
                    const float sF = ntF + g_nc[1][c + ec] - 2.0f * acc[1][i][j][h * 2 + ec];
                    const float d1 = sqrt_ap(fmaxf(sR, 0.0f));
                    const float d2 = sqrt_ap(fmaxf(sF, 0.0f));
                    o[ec] = wr * __expf(-d1) + wf * __expf(-d2);
                }
                rs += o[0] + o[1];
                *reinterpret_cast<float2*>(out + (size_t)q * Cn + c) = make_float2(o[0], o[1]);
            }
            rs += __shfl_xor_sync(0xffffffffu, rs, 1);
            rs += __shfl_xor_sync(0xffffffffu, rs, 2);
            if (cq == 0) g_psum[psIdx][q] = rs;
        }
    }
}

// ---------------------------------------------------------------------------
// Kernel 3: fused rowsum + streaming scale.
// One block per row. All threads issue their row loads first (long-latency,
// in flight across the barrier-free region); warp 0 concurrently folds the
// 128 psum partials (fixed order per lane group), then one sync and scale.
// ---------------------------------------------------------------------------
__global__ __launch_bounds__(256) void scale_kernel(float* __restrict__ out)
{
    const int q = blockIdx.x;
    float4* rowp = reinterpret_cast<float4*>(out + (size_t)q * Cn);
    __shared__ float sinv;

    float4 v[4];
    #pragma unroll
    for (int rr = 0; rr < 4; ++rr)
        v[rr] = rowp[threadIdx.x + rr * 256];

    if (threadIdx.x < 32) {
        float s = g_psum[threadIdx.x][q]
                + g_psum[threadIdx.x + 32][q]
                + g_psum[threadIdx.x + 64][q]
                + g_psum[threadIdx.x + 96][q];
        #pragma unroll
        for (int o = 16; o > 0; o >>= 1) s += __shfl_xor_sync(0xffffffffu, s, o);
        if (threadIdx.x == 0) sinv = 1.0f / s;
    }
    __syncthreads();
    const float inv = sinv;

    #pragma unroll
    for (int rr = 0; rr < 4; ++rr) {
        v[rr].x *= inv; v[rr].y *= inv; v[rr].z *= inv; v[rr].w *= inv;
        rowp[threadIdx.x + rr * 256] = v[rr];
    }
}

// ---------------------------------------------------------------------------
// Entry point
// ---------------------------------------------------------------------------
extern "C" void kernel_launch(void* const* d_in, const int* in_sizes, int n_in,
                              void* d_out, int out_size)
{
    const float* c_rgb  = (const float*)d_in[0];
    const float* c_flow = (const float*)d_in[1];
    const float* t_rgb  = (const float*)d_in[2];
    const float* t_flow = (const float*)d_in[3];
    const float* cr     = (const float*)d_in[4];
    const float* cf     = (const float*)d_in[5];
    float* out = (float*)d_out;

    cudaFuncSetAttribute(fused_mma_kernel,
                         cudaFuncAttributeMaxDynamicSharedMemorySize, SMEM_TOTAL);

    prep_kernel<<<2 * (Qn + Cn), 128>>>(t_rgb, t_flow, c_rgb, c_flow);

    dim3 grid(NCTA_C, Qn / BM);   // (64, 32) = 2048 CTAs
    fused_mma_kernel<<<grid, 256, SMEM_TOTAL>>>(cr, cf, out);

    scale_kernel<<<Qn, 256>>>(out);
}

// round 11
// speedup vs baseline: 1.4620x; 1.4620x over previous
#include <cuda_runtime.h>
#include <cuda_fp16.h>
#include <cstdint>

// Problem constants
constexpr int Qn = 4096, Cn = 4096, Dn = 1024;
#define EPSV 1e-6f

// GEMM config: CTA 128(M) x 64(N), KC=32 halfs, 3-stage cp.async, 256 threads
// 8 warps as 4(m) x 2(n); warp tile 32x32. Occupancy 2.
constexpr int BM = 128, BN = 64, KC = 32;
constexpr int NK = Dn / KC;                 // 32
constexpr int STAGES = 3;
constexpr int RSTRIDE = 80;                 // bytes per 32-half row (64B data + 16B pad)
constexpr int MOD_A = 128 * RSTRIDE;        // 10240
constexpr int MOD_B = 64 * RSTRIDE;         // 5120
constexpr int BOFF = 2 * MOD_A;             // 20480
constexpr int STAGE_BYTES = 2 * MOD_A + 2 * MOD_B;  // 30720
constexpr int SMEM_TOTAL = STAGES * STAGE_BYTES;    // 92160 (x2 CTAs = 184320)
constexpr int NCTA_C = Cn / BN;             // 64 column tiles

// Scratch (static __device__ — no cudaMalloc allowed)
__device__ __half g_h[4][(size_t)Qn * Dn];  // 0=c_rgb 1=c_flow 2=t_rgb(+eps) 3=t_flow(+eps)
__device__ float g_nt[2][Qn];
__device__ float g_nc[2][Cn];
__device__ float g_psum[2 * NCTA_C][Qn];    // per-(colTile,warp-half) row partial sums
__device__ float g_inv[Qn];                 // 1 / rowsum

// ---------------------------------------------------------------------------
// helpers
// ---------------------------------------------------------------------------
__device__ __forceinline__ uint32_t smem_u32(const void* p) {
    uint32_t a;
    asm("{ .reg .u64 t; cvta.to.shared.u64 t, %1; cvt.u32.u64 %0, t; }"
        : "=r"(a) : "l"(p));
    return a;
}
__device__ __forceinline__ void cp16(uint32_t saddr, const void* g) {
    asm volatile(
        "{ .reg .u64 gg; cvta.to.global.u64 gg, %1; "
        "cp.async.cg.shared.global [%0], [gg], 16; }"
        :: "r"(saddr), "l"(g));
}
__device__ __forceinline__ float sqrt_ap(float x) {
    float r; asm("sqrt.approx.f32 %0, %1;" : "=f"(r) : "f"(x)); return r;
}
#define LDSM_X4(r0, r1, r2, r3, addr) \
    asm volatile("ldmatrix.sync.aligned.m8n8.x4.shared.b16 {%0,%1,%2,%3}, [%4];" \
        : "=r"(r0), "=r"(r1), "=r"(r2), "=r"(r3) : "r"(addr))
#define MMA16816(d, a, b) \
    asm volatile( \
        "mma.sync.aligned.m16n8k16.row.col.f32.f16.f16.f32 " \
        "{%0,%1,%2,%3}, {%4,%5,%6,%7}, {%8,%9}, {%0,%1,%2,%3};" \
        : "+f"((d)[0]), "+f"((d)[1]), "+f"((d)[2]), "+f"((d)[3]) \
        : "r"((a)[0]), "r"((a)[1]), "r"((a)[2]), "r"((a)[3]), \
          "r"((b)[0]), "r"((b)[1]))

// ---------------------------------------------------------------------------
// Kernel 1: convert f32 -> f16 (rn, targets +eps first) + fp32 row norms
// ---------------------------------------------------------------------------
__global__ __launch_bounds__(128) void prep_kernel(
    const float* __restrict__ t_rgb, const float* __restrict__ t_flow,
    const float* __restrict__ c_rgb, const float* __restrict__ c_flow)
{
    int b = blockIdx.x;
    const float* src; float* dstN; __half* dstH; float eps;
    if (b < Qn)               { src = t_rgb  + (size_t)b * Dn;                 dstN = &g_nt[0][b];               dstH = g_h[2] + (size_t)b * Dn;                 eps = EPSV; }
    else if (b < 2 * Qn)      { src = t_flow + (size_t)(b - Qn) * Dn;          dstN = &g_nt[1][b - Qn];          dstH = g_h[3] + (size_t)(b - Qn) * Dn;          eps = EPSV; }
    else if (b < 2 * Qn + Cn) { src = c_rgb  + (size_t)(b - 2 * Qn) * Dn;      dstN = &g_nc[0][b - 2 * Qn];      dstH = g_h[0] + (size_t)(b - 2 * Qn) * Dn;      eps = 0.0f; }
    else                      { src = c_flow + (size_t)(b - 2 * Qn - Cn) * Dn; dstN = &g_nc[1][b - 2 * Qn - Cn]; dstH = g_h[1] + (size_t)(b - 2 * Qn - Cn) * Dn; eps = 0.0f; }

    float4 v0 = reinterpret_cast<const float4*>(src)[threadIdx.x];
    float4 v1 = reinterpret_cast<const float4*>(src)[threadIdx.x + 128];
    v0.x += eps; v0.y += eps; v0.z += eps; v0.w += eps;
    v1.x += eps; v1.y += eps; v1.z += eps; v1.w += eps;

    __half2* hp0 = reinterpret_cast<__half2*>(dstH) + threadIdx.x * 2;
    hp0[0] = __floats2half2_rn(v0.x, v0.y);
    hp0[1] = __floats2half2_rn(v0.z, v0.w);
    __half2* hp1 = reinterpret_cast<__half2*>(dstH) + (threadIdx.x + 128) * 2;
    hp1[0] = __floats2half2_rn(v1.x, v1.y);
    hp1[1] = __floats2half2_rn(v1.z, v1.w);

    float s = v0.x * v0.x + v0.y * v0.y + v0.z * v0.z + v0.w * v0.w
            + v1.x * v1.x + v1.y * v1.y + v1.z * v1.z + v1.w * v1.w;
    __shared__ float red[4];
    #pragma unroll
    for (int o = 16; o > 0; o >>= 1) s += __shfl_xor_sync(0xffffffffu, s, o);
    if ((threadIdx.x & 31) == 0) red[threadIdx.x >> 5] = s;
    __syncthreads();
    if (threadIdx.x < 4) {
        s = red[threadIdx.x];
        #pragma unroll
        for (int o = 2; o > 0; o >>= 1) s += __shfl_xor_sync(0xfu, s, o);
        if (threadIdx.x == 0) *dstN = s;
    }
}

// ---------------------------------------------------------------------------
// Kernel 2: dual f16 mma GEMM (128x64 CTA, 8 warps 4x2, 32x32 warp tile)
//           + fused distance/exp/mix epilogue + per-row partial sums
// ---------------------------------------------------------------------------
__global__ __launch_bounds__(256, 2) void fused_mma_kernel(
    const float* __restrict__ crP, const float* __restrict__ cfP,
    float* __restrict__ out)
{
    extern __shared__ char smem[];
    const uint32_t sb = smem_u32(smem);
    const int tid = threadIdx.x, wid = tid >> 5, l = tid & 31;
    const int wm = wid & 3, wn = wid >> 2;
    const int q0 = blockIdx.y * BM, c0 = blockIdx.x * BN;

    // --- loader mapping: 6 x 16B chunks per thread per stage ---
    const __half* gSrc[6]; uint32_t sDst[6];
    #pragma unroll
    for (int it = 0; it < 6; ++it) {
        const int id = tid + it * 256;            // 0..1535
        if (id < 1024) {
            const int mod = id >> 9, rem = id & 511;
            const int row = rem >> 2, c16 = rem & 3;
            gSrc[it] = g_h[2 + mod] + (size_t)(q0 + row) * Dn + c16 * 8;
            sDst[it] = (uint32_t)(mod * MOD_A + row * RSTRIDE + c16 * 16);
        } else {
            const int id2 = id - 1024;
            const int mod = id2 >> 8, rem = id2 & 255;
            const int row = rem >> 2, c16 = rem & 3;
            gSrc[it] = g_h[mod] + (size_t)(c0 + row) * Dn + c16 * 8;
            sDst[it] = (uint32_t)(BOFF + mod * MOD_B + row * RSTRIDE + c16 * 16);
        }
    }
    auto issue_stage = [&](int kc) {
        const uint32_t stg = sb + (uint32_t)(kc % STAGES) * STAGE_BYTES;
        const int ko = kc * KC;
        #pragma unroll
        for (int it = 0; it < 6; ++it)
            cp16(stg + sDst[it], gSrc[it] + ko);
        asm volatile("cp.async.commit_group;" ::: "memory");
    };

    // --- ldmatrix lane offsets (80B padded rows -> conflict-free) ---
    const uint32_t aOff = (uint32_t)(((l & 7) + ((l >> 3) & 1) * 8) * RSTRIDE
                                     + ((l >> 4) & 1) * 16);
    const uint32_t bOff4 = (uint32_t)(((l & 7) + ((l >> 4) & 1) * 8) * RSTRIDE
                                      + ((l >> 3) & 1) * 16);
    const uint32_t aBase = (uint32_t)(wm * 32 * RSTRIDE);
    const uint32_t bBase = (uint32_t)(BOFF + wn * 32 * RSTRIDE);

    float acc[2][2][4][4];   // [mod][m-frag(16)][n-frag(8)][e]
    #pragma unroll
    for (int m = 0; m < 2; ++m)
        #pragma unroll
        for (int i = 0; i < 2; ++i)
            #pragma unroll
            for (int j = 0; j < 4; ++j)
                #pragma unroll
                for (int e = 0; e < 4; ++e) acc[m][i][j][e] = 0.0f;

    issue_stage(0); issue_stage(1);

    for (int kc = 0; kc < NK; ++kc) {
        if (kc < NK - 1) asm volatile("cp.async.wait_group 1;" ::: "memory");
        else             asm volatile("cp.async.wait_group 0;" ::: "memory");
        __syncthreads();
        if (kc + 2 < NK) issue_stage(kc + 2);

        const uint32_t stg = sb + (uint32_t)(kc % STAGES) * STAGE_BYTES;
        #pragma unroll
        for (int s = 0; s < 2; ++s) {             // two k16 steps per KC=32
            #pragma unroll
            for (int m = 0; m < 2; ++m) {         // modality
                const uint32_t Am = stg + (uint32_t)(m * MOD_A) + aBase + s * 32 + aOff;
                const uint32_t Bm = stg + (uint32_t)(m * MOD_B) + bBase + s * 32 + bOff4;
                uint32_t a[2][4], b8[4][2];
                LDSM_X4(a[0][0], a[0][1], a[0][2], a[0][3], Am);
                LDSM_X4(a[1][0], a[1][1], a[1][2], a[1][3], Am + 16 * RSTRIDE);
                LDSM_X4(b8[0][0], b8[0][1], b8[1][0], b8[1][1], Bm);
                LDSM_X4(b8[2][0], b8[2][1], b8[3][0], b8[3][1], Bm + 16 * RSTRIDE);
                #pragma unroll
                for (int i = 0; i < 2; ++i)
                    #pragma unroll
                    for (int j = 0; j < 4; ++j)
                        MMA16816(acc[m][i][j], a[i], b8[j]);
            }
        }
    }

    // --- fused epilogue (+ deterministic per-row partial sums) ---
    const int r = l >> 2, cq = l & 3;
    const int psIdx = blockIdx.x * 2 + wn;
    #pragma unroll
    for (int i = 0; i < 2; ++i) {
        #pragma unroll
        for (int h = 0; h < 2; ++h) {
            const int q = q0 + wm * 32 + i * 16 + r + h * 8;
            const float ntR = g_nt[0][q], ntF = g_nt[1][q];
            const float rr = __ldg(crP + q), ff = __ldg(cfP + q);
            const float inv = 1.0f / (rr + ff);
            const float wr = rr * inv, wf = ff * inv;
            float rs = 0.0f;
            #pragma unroll
            for (int j = 0; j < 4; ++j) {
                const int c = c0 + wn * 32 + j * 8 + 2 * cq;
                float o[2];
                #pragma unroll
                for (int ec = 0; ec < 2; ++ec) {
                    const float sR = ntR + g_nc[0][c + ec] - 2.0f * acc[0][i][j][h * 2 + ec];
                    const float sF = ntF + g_nc[1][c + ec] - 2.0f * acc[1][i][j][h * 2 + ec];
                    const float d1 = sqrt_ap(fmaxf(sR, 0.0f));
                    const float d2 = sqrt_ap(fmaxf(sF, 0.0f));
                    o[ec] = wr * __expf(-d1) + wf * __expf(-d2);
                }
                rs += o[0] + o[1];
                *reinterpret_cast<float2*>(out + (size_t)q * Cn + c) = make_float2(o[0], o[1]);
            }
            rs += __shfl_xor_sync(0xffffffffu, rs, 1);
            rs += __shfl_xor_sync(0xffffffffu, rs, 2);
            if (cq == 0) g_psum[psIdx][q] = rs;
        }
    }
}

// ---------------------------------------------------------------------------
// Kernel 3a: fold 128 partial sums per row -> g_inv (fixed order, deterministic)
// ---------------------------------------------------------------------------
__global__ __launch_bounds__(256) void rowsum_kernel()
{
    const int q = blockIdx.x * 256 + threadIdx.x;
    float s = 0.0f;
    #pragma unroll 8
    for (int c = 0; c < 2 * NCTA_C; ++c) s += g_psum[c][q];
    g_inv[q] = 1.0f / s;
}

// ---------------------------------------------------------------------------
// Kernel 3b: streaming scale (no reductions, no barriers on critical path)
// ---------------------------------------------------------------------------
__global__ __launch_bounds__(256) void scale_kernel(float* __restrict__ out)
{
    const int q = blockIdx.x;
    const float inv = g_inv[q];
    float4* rowp = reinterpret_cast<float4*>(out + (size_t)q * Cn);
    #pragma unroll
    for (int rr = 0; rr < 4; ++rr) {
        float4 v = rowp[threadIdx.x + rr * 256];
        v.x *= inv; v.y *= inv; v.z *= inv; v.w *= inv;
        rowp[threadIdx.x + rr * 256] = v;
    }
}

// ---------------------------------------------------------------------------
// Entry point
// ---------------------------------------------------------------------------
extern "C" void kernel_launch(void* const* d_in, const int* in_sizes, int n_in,
                              void* d_out, int out_size)
{
    const float* c_rgb  = (const float*)d_in[0];
    const float* c_flow = (const float*)d_in[1];
    const float* t_rgb  = (const float*)d_in[2];
    const float* t_flow = (const float*)d_in[3];
    const float* cr     = (const float*)d_in[4];
    const float* cf     = (const float*)d_in[5];
    float* out = (float*)d_out;

    cudaFuncSetAttribute(fused_mma_kernel,
                         cudaFuncAttributeMaxDynamicSharedMemorySize, SMEM_TOTAL);

    prep_kernel<<<2 * (Qn + Cn), 128>>>(t_rgb, t_flow, c_rgb, c_flow);

    dim3 grid(NCTA_C, Qn / BM);   // (64, 32) = 2048 CTAs
    fused_mma_kernel<<<grid, 256, SMEM_TOTAL>>>(cr, cf, out);

    rowsum_kernel<<<Qn / 256, 256>>>();
    scale_kernel<<<Qn, 256>>>(out);
}

// round 12
// speedup vs baseline: 1.4696x; 1.0052x over previous
#include <cuda_runtime.h>
#include <cuda_fp16.h>
#include <cstdint>

// Problem constants
constexpr int Qn = 4096, Cn = 4096, Dn = 1024;
#define EPSV 1e-6f
#define EXP_OFF 45.0f   // range shift: stored o' = e^{OFF}*o; divides out in normalize

// GEMM config: CTA 128(M) x 64(N), KC=32 halfs, 3-stage cp.async, 256 threads
// 8 warps as 4(m) x 2(n); warp tile 32x32. Occupancy 2.
constexpr int BM = 128, BN = 64, KC = 32;
constexpr int NK = Dn / KC;                 // 32
constexpr int STAGES = 3;
constexpr int RSTRIDE = 80;                 // bytes per 32-half row (64B data + 16B pad)
constexpr int MOD_A = 128 * RSTRIDE;        // 10240
constexpr int MOD_B = 64 * RSTRIDE;         // 5120
constexpr int BOFF = 2 * MOD_A;             // 20480
constexpr int STAGE_BYTES = 2 * MOD_A + 2 * MOD_B;  // 30720
constexpr int SMEM_TOTAL = STAGES * STAGE_BYTES;    // 92160 (x2 CTAs = 184320)
constexpr int NCTA_C = Cn / BN;             // 64 column tiles

// Scratch (static __device__ — no cudaMalloc allowed)
__device__ __half g_h[4][(size_t)Qn * Dn];  // 0=c_rgb 1=c_flow 2=t_rgb(+eps) 3=t_flow(+eps)
__device__ __half g_o16[(size_t)Qn * Cn];   // unnormalized posterior (range-shifted), f16
__device__ float g_nt[2][Qn];
__device__ float g_nc[2][Cn];
__device__ float g_psum[2 * NCTA_C][Qn];    // per-(colTile,warp-half) row partial sums
__device__ float g_inv[Qn];                 // 1 / rowsum (of shifted values)

// ---------------------------------------------------------------------------
// helpers
// ---------------------------------------------------------------------------
__device__ __forceinline__ uint32_t smem_u32(const void* p) {
    uint32_t a;
    asm("{ .reg .u64 t; cvta.to.shared.u64 t, %1; cvt.u32.u64 %0, t; }"
        : "=r"(a) : "l"(p));
    return a;
}
__device__ __forceinline__ void cp16(uint32_t saddr, const void* g) {
    asm volatile(
        "{ .reg .u64 gg; cvta.to.global.u64 gg, %1; "
        "cp.async.cg.shared.global [%0], [gg], 16; }"
        :: "r"(saddr), "l"(g));
}
__device__ __forceinline__ float sqrt_ap(float x) {
    float r; asm("sqrt.approx.f32 %0, %1;" : "=f"(r) : "f"(x)); return r;
}
#define LDSM_X4(r0, r1, r2, r3, addr) \
    asm volatile("ldmatrix.sync.aligned.m8n8.x4.shared.b16 {%0,%1,%2,%3}, [%4];" \
        : "=r"(r0), "=r"(r1), "=r"(r2), "=r"(r3) : "r"(addr))
#define MMA16816(d, a, b) \
    asm volatile( \
        "mma.sync.aligned.m16n8k16.row.col.f32.f16.f16.f32 " \
        "{%0,%1,%2,%3}, {%4,%5,%6,%7}, {%8,%9}, {%0,%1,%2,%3};" \
        : "+f"((d)[0]), "+f"((d)[1]), "+f"((d)[2]), "+f"((d)[3]) \
        : "r"((a)[0]), "r"((a)[1]), "r"((a)[2]), "r"((a)[3]), \
          "r"((b)[0]), "r"((b)[1]))

// ---------------------------------------------------------------------------
// Kernel 1: convert f32 -> f16 (rn, targets +eps first) + fp32 row norms
// ---------------------------------------------------------------------------
__global__ __launch_bounds__(128) void prep_kernel(
    const float* __restrict__ t_rgb, const float* __restrict__ t_flow,
    const float* __restrict__ c_rgb, const float* __restrict__ c_flow)
{
    int b = blockIdx.x;
    const float* src; float* dstN; __half* dstH; float eps;
    if (b < Qn)               { src = t_rgb  + (size_t)b * Dn;                 dstN = &g_nt[0][b];               dstH = g_h[2] + (size_t)b * Dn;                 eps = EPSV; }
    else if (b < 2 * Qn)      { src = t_flow + (size_t)(b - Qn) * Dn;          dstN = &g_nt[1][b - Qn];          dstH = g_h[3] + (size_t)(b - Qn) * Dn;          eps = EPSV; }
    else if (b < 2 * Qn + Cn) { src = c_rgb  + (size_t)(b - 2 * Qn) * Dn;      dstN = &g_nc[0][b - 2 * Qn];      dstH = g_h[0] + (size_t)(b - 2 * Qn) * Dn;      eps = 0.0f; }
    else                      { src = c_flow + (size_t)(b - 2 * Qn - Cn) * Dn; dstN = &g_nc[1][b - 2 * Qn - Cn]; dstH = g_h[1] + (size_t)(b - 2 * Qn - Cn) * Dn; eps = 0.0f; }

    float4 v0 = reinterpret_cast<const float4*>(src)[threadIdx.x];
    float4 v1 = reinterpret_cast<const float4*>(src)[threadIdx.x + 128];
    v0.x += eps; v0.y += eps; v0.z += eps; v0.w += eps;
    v1.x += eps; v1.y += eps; v1.z += eps; v1.w += eps;

    __half2* hp0 = reinterpret_cast<__half2*>(dstH) + threadIdx.x * 2;
    hp0[0] = __floats2half2_rn(v0.x, v0.y);
    hp0[1] = __floats2half2_rn(v0.z, v0.w);
    __half2* hp1 = reinterpret_cast<__half2*>(dstH) + (threadIdx.x + 128) * 2;
    hp1[0] = __floats2half2_rn(v1.x, v1.y);
    hp1[1] = __floats2half2_rn(v1.z, v1.w);

    float s = v0.x * v0.x + v0.y * v0.y + v0.z * v0.z + v0.w * v0.w
            + v1.x * v1.x + v1.y * v1.y + v1.z * v1.z + v1.w * v1.w;
    __shared__ float red[4];
    #pragma unroll
    for (int o = 16; o > 0; o >>= 1) s += __shfl_xor_sync(0xffffffffu, s, o);
    if ((threadIdx.x & 31) == 0) red[threadIdx.x >> 5] = s;
    __syncthreads();
    if (threadIdx.x < 4) {
        s = red[threadIdx.x];
        #pragma unroll
        for (int o = 2; o > 0; o >>= 1) s += __shfl_xor_sync(0xfu, s, o);
        if (threadIdx.x == 0) *dstN = s;
    }
}

// ---------------------------------------------------------------------------
// Kernel 2: dual f16 mma GEMM (128x64 CTA, 8 warps 4x2, 32x32 warp tile)
//           + fused distance/exp/mix epilogue (f16, range-shifted) + psums
// ---------------------------------------------------------------------------
__global__ __launch_bounds__(256, 2) void fused_mma_kernel(
    const float* __restrict__ crP, const float* __restrict__ cfP)
{
    extern __shared__ char smem[];
    const uint32_t sb = smem_u32(smem);
    const int tid = threadIdx.x, wid = tid >> 5, l = tid & 31;
    const int wm = wid & 3, wn = wid >> 2;
    const int q0 = blockIdx.y * BM, c0 = blockIdx.x * BN;

    // --- loader mapping: 6 x 16B chunks per thread per stage ---
    const __half* gSrc[6]; uint32_t sDst[6];
    #pragma unroll
    for (int it = 0; it < 6; ++it) {
        const int id = tid + it * 256;            // 0..1535
        if (id < 1024) {
            const int mod = id >> 9, rem = id & 511;
            const int row = rem >> 2, c16 = rem & 3;
            gSrc[it] = g_h[2 + mod] + (size_t)(q0 + row) * Dn + c16 * 8;
            sDst[it] = (uint32_t)(mod * MOD_A + row * RSTRIDE + c16 * 16);
        } else {
            const int id2 = id - 1024;
            const int mod = id2 >> 8, rem = id2 & 255;
            const int row = rem >> 2, c16 = rem & 3;
            gSrc[it] = g_h[mod] + (size_t)(c0 + row) * Dn + c16 * 8;
            sDst[it] = (uint32_t)(BOFF + mod * MOD_B + row * RSTRIDE + c16 * 16);
        }
    }
    auto issue_stage = [&](int kc) {
        const uint32_t stg = sb + (uint32_t)(kc % STAGES) * STAGE_BYTES;
        const int ko = kc * KC;
        #pragma unroll
        for (int it = 0; it < 6; ++it)
            cp16(stg + sDst[it], gSrc[it] + ko);
        asm volatile("cp.async.commit_group;" ::: "memory");
    };

    // --- ldmatrix lane offsets (80B padded rows -> conflict-free) ---
    const uint32_t aOff = (uint32_t)(((l & 7) + ((l >> 3) & 1) * 8) * RSTRIDE
                                     + ((l >> 4) & 1) * 16);
    const uint32_t bOff4 = (uint32_t)(((l & 7) + ((l >> 4) & 1) * 8) * RSTRIDE
                                      + ((l >> 3) & 1) * 16);
    const uint32_t aBase = (uint32_t)(wm * 32 * RSTRIDE);
    const uint32_t bBase = (uint32_t)(BOFF + wn * 32 * RSTRIDE);

    float acc[2][2][4][4];   // [mod][m-frag(16)][n-frag(8)][e]
    #pragma unroll
    for (int m = 0; m < 2; ++m)
        #pragma unroll
        for (int i = 0; i < 2; ++i)
            #pragma unroll
            for (int j = 0; j < 4; ++j)
                #pragma unroll
                for (int e = 0; e < 4; ++e) acc[m][i][j][e] = 0.0f;

    issue_stage(0); issue_stage(1);

    for (int kc = 0; kc < NK; ++kc) {
        if (kc < NK - 1) asm volatile("cp.async.wait_group 1;" ::: "memory");
        else             asm volatile("cp.async.wait_group 0;" ::: "memory");
        __syncthreads();
        if (kc + 2 < NK) issue_stage(kc + 2);

        const uint32_t stg = sb + (uint32_t)(kc % STAGES) * STAGE_BYTES;
        #pragma unroll
        for (int s = 0; s < 2; ++s) {             // two k16 steps per KC=32
            #pragma unroll
            for (int m = 0; m < 2; ++m) {         // modality
                const uint32_t Am = stg + (uint32_t)(m * MOD_A) + aBase + s * 32 + aOff;
                const uint32_t Bm = stg + (uint32_t)(m * MOD_B) + bBase + s * 32 + bOff4;
                uint32_t a[2][4], b8[4][2];
                LDSM_X4(a[0][0], a[0][1], a[0][2], a[0][3], Am);
                LDSM_X4(a[1][0], a[1][1], a[1][2], a[1][3], Am + 16 * RSTRIDE);
                LDSM_X4(b8[0][0], b8[0][1], b8[1][0], b8[1][1], Bm);
                LDSM_X4(b8[2][0], b8[2][1], b8[3][0], b8[3][1], Bm + 16 * RSTRIDE);
                #pragma unroll
                for (int i = 0; i < 2; ++i)
                    #pragma unroll
                    for (int j = 0; j < 4; ++j)
                        MMA16816(acc[m][i][j], a[i], b8[j]);
            }
        }
    }

    // --- fused epilogue: o' = wr*e^{OFF-d1} + wf*e^{OFF-d2}, stored f16 ---
    const int r = l >> 2, cq = l & 3;
    const int psIdx = blockIdx.x * 2 + wn;
    #pragma unroll
    for (int i = 0; i < 2; ++i) {
        #pragma unroll
        for (int h = 0; h < 2; ++h) {
            const int q = q0 + wm * 32 + i * 16 + r + h * 8;
            const float ntR = g_nt[0][q], ntF = g_nt[1][q];
            const float rr = __ldg(crP + q), ff = __ldg(cfP + q);
            const float inv = 1.0f / (rr + ff);
            const float wr = rr * inv, wf = ff * inv;
            float rs = 0.0f;
            #pragma unroll
            for (int j = 0; j < 4; ++j) {
                const int c = c0 + wn * 32 + j * 8 + 2 * cq;
                float o[2];
                #pragma unroll
                for (int ec = 0; ec < 2; ++ec) {
                    const float sR = ntR + g_nc[0][c + ec] - 2.0f * acc[0][i][j][h * 2 + ec];
                    const float sF = ntF + g_nc[1][c + ec] - 2.0f * acc[1][i][j][h * 2 + ec];
                    const float d1 = sqrt_ap(fmaxf(sR, 0.0f));
                    const float d2 = sqrt_ap(fmaxf(sF, 0.0f));
                    o[ec] = wr * __expf(EXP_OFF - d1) + wf * __expf(EXP_OFF - d2);
                }
                rs += o[0] + o[1];
                *reinterpret_cast<__half2*>(g_o16 + (size_t)q * Cn + c) =
                    __floats2half2_rn(o[0], o[1]);
            }
            rs += __shfl_xor_sync(0xffffffffu, rs, 1);
            rs += __shfl_xor_sync(0xffffffffu, rs, 2);
            if (cq == 0) g_psum[psIdx][q] = rs;
        }
    }
}

// ---------------------------------------------------------------------------
// Kernel 3a: fold 128 partial sums per row -> g_inv (fixed order, deterministic)
// ---------------------------------------------------------------------------
__global__ __launch_bounds__(256) void rowsum_kernel()
{
    const int q = blockIdx.x * 256 + threadIdx.x;
    float s = 0.0f;
    #pragma unroll 8
    for (int c = 0; c < 2 * NCTA_C; ++c) s += g_psum[c][q];
    g_inv[q] = 1.0f / s;
}

// ---------------------------------------------------------------------------
// Kernel 3b: streaming scale f16 -> f32 out (no reductions on critical path)
// Each thread: 16 halfs in (32B), 16 floats out (64B).
// ---------------------------------------------------------------------------
__global__ __launch_bounds__(256) void scale_kernel(float* __restrict__ out)
{
    const int q = blockIdx.x;
    const float inv = g_inv[q];
    const uint4* src = reinterpret_cast<const uint4*>(g_o16 + (size_t)q * Cn);
    float4* dst = reinterpret_cast<float4*>(out + (size_t)q * Cn);

    #pragma unroll
    for (int half16 = 0; half16 < 2; ++half16) {
        const int idx = threadIdx.x + half16 * 256;   // which 8-half group
        uint4 pk = src[idx];
        const __half2* h2 = reinterpret_cast<const __half2*>(&pk);
        float4 o0, o1;
        float2 t;
        t = __half22float2(h2[0]); o0.x = t.x * inv; o0.y = t.y * inv;
        t = __half22float2(h2[1]); o0.z = t.x * inv; o0.w = t.y * inv;
        t = __half22float2(h2[2]); o1.x = t.x * inv; o1.y = t.y * inv;
        t = __half22float2(h2[3]); o1.z = t.x * inv; o1.w = t.y * inv;
        dst[idx * 2 + 0] = o0;
        dst[idx * 2 + 1] = o1;
    }
}

// ---------------------------------------------------------------------------
// Entry point
// ---------------------------------------------------------------------------
extern "C" void kernel_launch(void* const* d_in, const int* in_sizes, int n_in,
                              void* d_out, int out_size)
{
    const float* c_rgb  = (const float*)d_in[0];
    const float* c_flow = (const float*)d_in[1];
    const float* t_rgb  = (const float*)d_in[2];
    const float* t_flow = (const float*)d_in[3];
    const float* cr     = (const float*)d_in[4];
    const float* cf     = (const float*)d_in[5];
    float* out = (float*)d_out;

    cudaFuncSetAttribute(fused_mma_kernel,
                         cudaFuncAttributeMaxDynamicSharedMemorySize, SMEM_TOTAL);

    prep_kernel<<<2 * (Qn + Cn), 128>>>(t_rgb, t_flow, c_rgb, c_flow);

    dim3 grid(NCTA_C, Qn / BM);   // (64, 32) = 2048 CTAs
    fused_mma_kernel<<<grid, 256, SMEM_TOTAL>>>(cr, cf);

    rowsum_kernel<<<Qn / 256, 256>>>();
    scale_kernel<<<Qn, 256>>>(out);
}

// round 13
// speedup vs baseline: 1.4812x; 1.0079x over previous
#include <cuda_runtime.h>
#include <cuda_fp16.h>
#include <cstdint>

// Problem constants
constexpr int Qn = 4096, Cn = 4096, Dn = 1024;
#define EPSV 1e-6f
#define EXP_OFF 45.0f   // range shift: stored o' = e^{OFF}*o; divides out in normalize

// GEMM config: CTA 128(M) x 64(N), KC=32 halfs, 3-stage cp.async, 256 threads
// 8 warps as 4(m) x 2(n); warp tile 32x32. Occupancy 2.
constexpr int BM = 128, BN = 64, KC = 32;
constexpr int NK = Dn / KC;                 // 32
constexpr int STAGES = 3;
constexpr int RSTRIDE = 80;                 // bytes per 32-half row (64B data + 16B pad)
constexpr int MOD_A = 128 * RSTRIDE;        // 10240
constexpr int MOD_B = 64 * RSTRIDE;         // 5120
constexpr int BOFF = 2 * MOD_A;             // 20480
constexpr int STAGE_BYTES = 2 * MOD_A + 2 * MOD_B;  // 30720
constexpr int SMEM_TOTAL = STAGES * STAGE_BYTES;    // 92160 (x2 CTAs = 184320)
constexpr int NCTA_C = Cn / BN;             // 64 column tiles

// Scratch (static __device__ — no cudaMalloc allowed)
__device__ __half g_h[4][(size_t)Qn * Dn];  // 0=c_rgb 1=c_flow 2=t_rgb(+eps) 3=t_flow(+eps)
__device__ __half g_o16[(size_t)Qn * Cn];   // unnormalized posterior (range-shifted), f16
__device__ float g_nt[2][Qn];
__device__ float g_nc[2][Cn];
__device__ float g_psum[2 * NCTA_C][Qn];    // per-(colTile,warp-half) row partial sums
__device__ float g_inv[Qn];                 // 1 / rowsum (of shifted values)

// ---------------------------------------------------------------------------
// helpers
// ---------------------------------------------------------------------------
__device__ __forceinline__ uint32_t smem_u32(const void* p) {
    uint32_t a;
    asm("{ .reg .u64 t; cvta.to.shared.u64 t, %1; cvt.u32.u64 %0, t; }"
        : "=r"(a) : "l"(p));
    return a;
}
__device__ __forceinline__ void cp16(uint32_t saddr, const void* g) {
    asm volatile(
        "{ .reg .u64 gg; cvta.to.global.u64 gg, %1; "
        "cp.async.cg.shared.global [%0], [gg], 16; }"
        :: "r"(saddr), "l"(g));
}
__device__ __forceinline__ float sqrt_ap(float x) {
    float r; asm("sqrt.approx.f32 %0, %1;" : "=f"(r) : "f"(x)); return r;
}
#define LDSM_X4(r0, r1, r2, r3, addr) \
    asm volatile("ldmatrix.sync.aligned.m8n8.x4.shared.b16 {%0,%1,%2,%3}, [%4];" \
        : "=r"(r0), "=r"(r1), "=r"(r2), "=r"(r3) : "r"(addr))
#define MMA16816(d, a, b) \
    asm volatile( \
        "mma.sync.aligned.m16n8k16.row.col.f32.f16.f16.f32 " \
        "{%0,%1,%2,%3}, {%4,%5,%6,%7}, {%8,%9}, {%0,%1,%2,%3};" \
        : "+f"((d)[0]), "+f"((d)[1]), "+f"((d)[2]), "+f"((d)[3]) \
        : "r"((a)[0]), "r"((a)[1]), "r"((a)[2]), "r"((a)[3]), \
          "r"((b)[0]), "r"((b)[1]))

// ---------------------------------------------------------------------------
// Kernel 1: convert f32 -> f16 (rn, targets +eps first) + fp32 row norms
// ---------------------------------------------------------------------------
__global__ __launch_bounds__(128) void prep_kernel(
    const float* __restrict__ t_rgb, const float* __restrict__ t_flow,
    const float* __restrict__ c_rgb, const float* __restrict__ c_flow)
{
    int b = blockIdx.x;
    const float* src; float* dstN; __half* dstH; float eps;
    if (b < Qn)               { src = t_rgb  + (size_t)b * Dn;                 dstN = &g_nt[0][b];               dstH = g_h[2] + (size_t)b * Dn;                 eps = EPSV; }
    else if (b < 2 * Qn)      { src = t_flow + (size_t)(b - Qn) * Dn;          dstN = &g_nt[1][b - Qn];          dstH = g_h[3] + (size_t)(b - Qn) * Dn;          eps = EPSV; }
    else if (b < 2 * Qn + Cn) { src = c_rgb  + (size_t)(b - 2 * Qn) * Dn;      dstN = &g_nc[0][b - 2 * Qn];      dstH = g_h[0] + (size_t)(b - 2 * Qn) * Dn;      eps = 0.0f; }
    else                      { src = c_flow + (size_t)(b - 2 * Qn - Cn) * Dn; dstN = &g_nc[1][b - 2 * Qn - Cn]; dstH = g_h[1] + (size_t)(b - 2 * Qn - Cn) * Dn; eps = 0.0f; }

    float4 v0 = reinterpret_cast<const float4*>(src)[threadIdx.x];
    float4 v1 = reinterpret_cast<const float4*>(src)[threadIdx.x + 128];
    v0.x += eps; v0.y += eps; v0.z += eps; v0.w += eps;
    v1.x += eps; v1.y += eps; v1.z += eps; v1.w += eps;

    __half2* hp0 = reinterpret_cast<__half2*>(dstH) + threadIdx.x * 2;
    hp0[0] = __floats2half2_rn(v0.x, v0.y);
    hp0[1] = __floats2half2_rn(v0.z, v0.w);
    __half2* hp1 = reinterpret_cast<__half2*>(dstH) + (threadIdx.x + 128) * 2;
    hp1[0] = __floats2half2_rn(v1.x, v1.y);
    hp1[1] = __floats2half2_rn(v1.z, v1.w);

    float s = v0.x * v0.x + v0.y * v0.y + v0.z * v0.z + v0.w * v0.w
            + v1.x * v1.x + v1.y * v1.y + v1.z * v1.z + v1.w * v1.w;
    __shared__ float red[4];
    #pragma unroll
    for (int o = 16; o > 0; o >>= 1) s += __shfl_xor_sync(0xffffffffu, s, o);
    if ((threadIdx.x & 31) == 0) red[threadIdx.x >> 5] = s;
    __syncthreads();
    if (threadIdx.x < 4) {
        s = red[threadIdx.x];
        #pragma unroll
        for (int o = 2; o > 0; o >>= 1) s += __shfl_xor_sync(0xfu, s, o);
        if (threadIdx.x == 0) *dstN = s;
    }
}

// ---------------------------------------------------------------------------
// Kernel 2: dual f16 mma GEMM (128x64 CTA, 8 warps 4x2, 32x32 warp tile)
//           + fused distance/exp/mix epilogue (f16, range-shifted) + psums
// ---------------------------------------------------------------------------
__global__ __launch_bounds__(256, 2) void fused_mma_kernel(
    const float* __restrict__ crP, const float* __restrict__ cfP)
{
    extern __shared__ char smem[];
    const uint32_t sb = smem_u32(smem);
    const int tid = threadIdx.x, wid = tid >> 5, l = tid & 31;
    const int wm = wid & 3, wn = wid >> 2;
    const int q0 = blockIdx.y * BM, c0 = blockIdx.x * BN;

    // --- loader mapping: 6 x 16B chunks per thread per stage ---
    const __half* gSrc[6]; uint32_t sDst[6];
    #pragma unroll
    for (int it = 0; it < 6; ++it) {
        const int id = tid + it * 256;            // 0..1535
        if (id < 1024) {
            const int mod = id >> 9, rem = id & 511;
            const int row = rem >> 2, c16 = rem & 3;
            gSrc[it] = g_h[2 + mod] + (size_t)(q0 + row) * Dn + c16 * 8;
            sDst[it] = (uint32_t)(mod * MOD_A + row * RSTRIDE + c16 * 16);
        } else {
            const int id2 = id - 1024;
            const int mod = id2 >> 8, rem = id2 & 255;
            const int row = rem >> 2, c16 = rem & 3;
            gSrc[it] = g_h[mod] + (size_t)(c0 + row) * Dn + c16 * 8;
            sDst[it] = (uint32_t)(BOFF + mod * MOD_B + row * RSTRIDE + c16 * 16);
        }
    }
    auto issue_stage = [&](int kc) {
        const uint32_t stg = sb + (uint32_t)(kc % STAGES) * STAGE_BYTES;
        const int ko = kc * KC;
        #pragma unroll
        for (int it = 0; it < 6; ++it)
            cp16(stg + sDst[it], gSrc[it] + ko);
        asm volatile("cp.async.commit_group;" ::: "memory");
    };

    // --- ldmatrix lane offsets (80B padded rows -> conflict-free) ---
    const uint32_t aOff = (uint32_t)(((l & 7) + ((l >> 3) & 1) * 8) * RSTRIDE
                                     + ((l >> 4) & 1) * 16);
    const uint32_t bOff4 = (uint32_t)(((l & 7) + ((l >> 4) & 1) * 8) * RSTRIDE
                                      + ((l >> 3) & 1) * 16);
    const uint32_t aBase = (uint32_t)(wm * 32 * RSTRIDE);
    const uint32_t bBase = (uint32_t)(BOFF + wn * 32 * RSTRIDE);

    float acc[2][2][4][4];   // [mod][m-frag(16)][n-frag(8)][e]
    #pragma unroll
    for (int m = 0; m < 2; ++m)
        #pragma unroll
        for (int i = 0; i < 2; ++i)
            #pragma unroll
            for (int j = 0; j < 4; ++j)
                #pragma unroll
                for (int e = 0; e < 4; ++e) acc[m][i][j][e] = 0.0f;

    issue_stage(0); issue_stage(1);

    for (int kc = 0; kc < NK; ++kc) {
        if (kc < NK - 1) asm volatile("cp.async.wait_group 1;" ::: "memory");
        else             asm volatile("cp.async.wait_group 0;" ::: "memory");
        __syncthreads();
        if (kc + 2 < NK) issue_stage(kc + 2);

        const uint32_t stg = sb + (uint32_t)(kc % STAGES) * STAGE_BYTES;
        #pragma unroll
        for (int s = 0; s < 2; ++s) {             // two k16 steps per KC=32
            #pragma unroll
            for (int m = 0; m < 2; ++m) {         // modality
                const uint32_t Am = stg + (uint32_t)(m * MOD_A) + aBase + s * 32 + aOff;
                const uint32_t Bm = stg + (uint32_t)(m * MOD_B) + bBase + s * 32 + bOff4;
                uint32_t a[2][4], b8[4][2];
                LDSM_X4(a[0][0], a[0][1], a[0][2], a[0][3], Am);
                LDSM_X4(a[1][0], a[1][1], a[1][2], a[1][3], Am + 16 * RSTRIDE);
                LDSM_X4(b8[0][0], b8[0][1], b8[1][0], b8[1][1], Bm);
                LDSM_X4(b8[2][0], b8[2][1], b8[3][0], b8[3][1], Bm + 16 * RSTRIDE);
                #pragma unroll
                for (int i = 0; i < 2; ++i)
                    #pragma unroll
                    for (int j = 0; j < 4; ++j)
                        MMA16816(acc[m][i][j], a[i], b8[j]);
            }
        }
    }

    // --- fused epilogue: o' = wr*e^{OFF-d1} + wf*e^{OFF-d2}, stored f16 ---
    const int r = l >> 2, cq = l & 3;
    const int psIdx = blockIdx.x * 2 + wn;
    #pragma unroll
    for (int i = 0; i < 2; ++i) {
        #pragma unroll
        for (int h = 0; h < 2; ++h) {
            const int q = q0 + wm * 32 + i * 16 + r + h * 8;
            const float ntR = g_nt[0][q], ntF = g_nt[1][q];
            const float rr = __ldg(crP + q), ff = __ldg(cfP + q);
            const float inv = 1.0f / (rr + ff);
            const float wr = rr * inv, wf = ff * inv;
            float rs = 0.0f;
            #pragma unroll
            for (int j = 0; j < 4; ++j) {
                const int c = c0 + wn * 32 + j * 8 + 2 * cq;
                float o[2];
                #pragma unroll
                for (int ec = 0; ec < 2; ++ec) {
                    const float sR = ntR + g_nc[0][c + ec] - 2.0f * acc[0][i][j][h * 2 + ec];
                    const float sF = ntF + g_nc[1][c + ec] - 2.0f * acc[1][i][j][h * 2 + ec];
                    const float d1 = sqrt_ap(fmaxf(sR, 0.0f));
                    const float d2 = sqrt_ap(fmaxf(sF, 0.0f));
                    o[ec] = wr * __expf(EXP_OFF - d1) + wf * __expf(EXP_OFF - d2);
                }
                rs += o[0] + o[1];
                *reinterpret_cast<__half2*>(g_o16 + (size_t)q * Cn + c) =
                    __floats2half2_rn(o[0], o[1]);
            }
            rs += __shfl_xor_sync(0xffffffffu, rs, 1);
            rs += __shfl_xor_sync(0xffffffffu, rs, 2);
            if (cq == 0) g_psum[psIdx][q] = rs;
        }
    }
}

// ---------------------------------------------------------------------------
// Kernel 3a: fold 128 partial sums per row -> g_inv (fixed order, deterministic)
// ---------------------------------------------------------------------------
__global__ __launch_bounds__(256) void rowsum_kernel()
{
    const int q = blockIdx.x * 256 + threadIdx.x;
    float s = 0.0f;
    #pragma unroll 8
    for (int c = 0; c < 2 * NCTA_C; ++c) s += g_psum[c][q];
    g_inv[q] = 1.0f / s;
}

// ---------------------------------------------------------------------------
// Kernel 3b: streaming scale f16 -> f32 out, fully coalesced both sides.
// Thread t handles output float4 index t + k*256 (k=0..3): load = consecutive
// uint2 (8B/lane, 256B/warp), store = consecutive float4 (16B/lane).
// ---------------------------------------------------------------------------
__global__ __launch_bounds__(256) void scale_kernel(float* __restrict__ out)
{
    const int q = blockIdx.x;
    const float inv = g_inv[q];
    const uint2* src = reinterpret_cast<const uint2*>(g_o16 + (size_t)q * Cn);  // 1024 groups of 4 halfs
    float4* dst = reinterpret_cast<float4*>(out + (size_t)q * Cn);              // 1024 float4

    #pragma unroll
    for (int k = 0; k < 4; ++k) {
        const int j = threadIdx.x + k * 256;
        uint2 pk = src[j];
        const __half2 h0 = *reinterpret_cast<const __half2*>(&pk.x);
        const __half2 h1 = *reinterpret_cast<const __half2*>(&pk.y);
        const float2 a = __half22float2(h0);
        const float2 b = __half22float2(h1);
        dst[j] = make_float4(a.x * inv, a.y * inv, b.x * inv, b.y * inv);
    }
}

// ---------------------------------------------------------------------------
// Entry point
// ---------------------------------------------------------------------------
extern "C" void kernel_launch(void* const* d_in, const int* in_sizes, int n_in,
                              void* d_out, int out_size)
{
    const float* c_rgb  = (const float*)d_in[0];
    const float* c_flow = (const float*)d_in[1];
    const float* t_rgb  = (const float*)d_in[2];
    const float* t_flow = (const float*)d_in[3];
    const float* cr     = (const float*)d_in[4];
    const float* cf     = (const float*)d_in[5];
    float* out = (float*)d_out;

    cudaFuncSetAttribute(fused_mma_kernel,
                         cudaFuncAttributeMaxDynamicSharedMemorySize, SMEM_TOTAL);

    prep_kernel<<<2 * (Qn + Cn), 128>>>(t_rgb, t_flow, c_rgb, c_flow);

    dim3 grid(NCTA_C, Qn / BM);   // (64, 32) = 2048 CTAs
    fused_mma_kernel<<<grid, 256, SMEM_TOTAL>>>(cr, cf);

    rowsum_kernel<<<Qn / 256, 256>>>();
    scale_kernel<<<Qn, 256>>>(out);
}

// round 14
// speedup vs baseline: 1.4897x; 1.0057x over previous
#include <cuda_runtime.h>
#include <cuda_fp16.h>
#include <cstdint>

// Problem constants
constexpr int Qn = 4096, Cn = 4096, Dn = 1024;
#define EPSV 1e-6f
#define EXP_OFF 45.0f   // range shift: stored o' = e^{OFF}*o; divides out in normalize

// GEMM config: CTA 128(M) x 64(N), KC=32 halfs, 3-stage cp.async, 256 threads
// 8 warps as 4(m) x 2(n); warp tile 32x32. Occupancy 2.
constexpr int BM = 128, BN = 64, KC = 32;
constexpr int NK = Dn / KC;                 // 32
constexpr int STAGES = 3;
constexpr int RSTRIDE = 80;                 // bytes per 32-half row (64B data + 16B pad)
constexpr int MOD_A = 128 * RSTRIDE;        // 10240
constexpr int MOD_B = 64 * RSTRIDE;         // 5120
constexpr int BOFF = 2 * MOD_A;             // 20480
constexpr int STAGE_BYTES = 2 * MOD_A + 2 * MOD_B;  // 30720
constexpr int SMEM_TOTAL = STAGES * STAGE_BYTES;    // 92160 (x2 CTAs = 184320)
constexpr int NCTA_C = Cn / BN;             // 64 column tiles

// Scratch (static __device__ — no cudaMalloc allowed)
__device__ __half g_h[4][(size_t)Qn * Dn];  // 0=c_rgb 1=c_flow 2=t_rgb(+eps) 3=t_flow(+eps)
__device__ __half g_o16[(size_t)Qn * Cn];   // unnormalized posterior (range-shifted), f16
__device__ float g_nt[2][Qn];
__device__ float g_nc[2][Cn];
__device__ float g_psum[2 * NCTA_C][Qn];    // per-(colTile,warp-half) row partial sums
__device__ float g_inv[Qn];                 // 1 / rowsum (of shifted values)

// ---------------------------------------------------------------------------
// helpers
// ---------------------------------------------------------------------------
__device__ __forceinline__ uint32_t smem_u32(const void* p) {
    uint32_t a;
    asm("{ .reg .u64 t; cvta.to.shared.u64 t, %1; cvt.u32.u64 %0, t; }"
        : "=r"(a) : "l"(p));
    return a;
}
__device__ __forceinline__ void cp16(uint32_t saddr, const void* g) {
    asm volatile(
        "{ .reg .u64 gg; cvta.to.global.u64 gg, %1; "
        "cp.async.cg.shared.global [%0], [gg], 16; }"
        :: "r"(saddr), "l"(g));
}
__device__ __forceinline__ float sqrt_ap(float x) {
    float r; asm("sqrt.approx.f32 %0, %1;" : "=f"(r) : "f"(x)); return r;
}
#define LDSM_X4(r0, r1, r2, r3, addr) \
    asm volatile("ldmatrix.sync.aligned.m8n8.x4.shared.b16 {%0,%1,%2,%3}, [%4];" \
        : "=r"(r0), "=r"(r1), "=r"(r2), "=r"(r3) : "r"(addr))
#define MMA16816(d, a, b) \
    asm volatile( \
        "mma.sync.aligned.m16n8k16.row.col.f32.f16.f16.f32 " \
        "{%0,%1,%2,%3}, {%4,%5,%6,%7}, {%8,%9}, {%0,%1,%2,%3};" \
        : "+f"((d)[0]), "+f"((d)[1]), "+f"((d)[2]), "+f"((d)[3]) \
        : "r"((a)[0]), "r"((a)[1]), "r"((a)[2]), "r"((a)[3]), \
          "r"((b)[0]), "r"((b)[1]))

// ---------------------------------------------------------------------------
// Kernel 1: convert f32 -> f16 (rn, targets +eps first) + fp32 row norms
// ---------------------------------------------------------------------------
__global__ __launch_bounds__(128) void prep_kernel(
    const float* __restrict__ t_rgb, const float* __restrict__ t_flow,
    const float* __restrict__ c_rgb, const float* __restrict__ c_flow)
{
    int b = blockIdx.x;
    const float* src; float* dstN; __half* dstH; float eps;
    if (b < Qn)               { src = t_rgb  + (size_t)b * Dn;                 dstN = &g_nt[0][b];               dstH = g_h[2] + (size_t)b * Dn;                 eps = EPSV; }
    else if (b < 2 * Qn)      { src = t_flow + (size_t)(b - Qn) * Dn;          dstN = &g_nt[1][b - Qn];          dstH = g_h[3] + (size_t)(b - Qn) * Dn;          eps = EPSV; }
    else if (b < 2 * Qn + Cn) { src = c_rgb  + (size_t)(b - 2 * Qn) * Dn;      dstN = &g_nc[0][b - 2 * Qn];      dstH = g_h[0] + (size_t)(b - 2 * Qn) * Dn;      eps = 0.0f; }
    else                      { src = c_flow + (size_t)(b - 2 * Qn - Cn) * Dn; dstN = &g_nc[1][b - 2 * Qn - Cn]; dstH = g_h[1] + (size_t)(b - 2 * Qn - Cn) * Dn; eps = 0.0f; }

    float4 v0 = reinterpret_cast<const float4*>(src)[threadIdx.x];
    float4 v1 = reinterpret_cast<const float4*>(src)[threadIdx.x + 128];
    v0.x += eps; v0.y += eps; v0.z += eps; v0.w += eps;
    v1.x += eps; v1.y += eps; v1.z += eps; v1.w += eps;

    __half2* hp0 = reinterpret_cast<__half2*>(dstH) + threadIdx.x * 2;
    hp0[0] = __floats2half2_rn(v0.x, v0.y);
    hp0[1] = __floats2half2_rn(v0.z, v0.w);
    __half2* hp1 = reinterpret_cast<__half2*>(dstH) + (threadIdx.x + 128) * 2;
    hp1[0] = __floats2half2_rn(v1.x, v1.y);
    hp1[1] = __floats2half2_rn(v1.z, v1.w);

    float s = v0.x * v0.x + v0.y * v0.y + v0.z * v0.z + v0.w * v0.w
            + v1.x * v1.x + v1.y * v1.y + v1.z * v1.z + v1.w * v1.w;
    __shared__ float red[4];
    #pragma unroll
    for (int o = 16; o > 0; o >>= 1) s += __shfl_xor_sync(0xffffffffu, s, o);
    if ((threadIdx.x & 31) == 0) red[threadIdx.x >> 5] = s;
    __syncthreads();
    if (threadIdx.x < 4) {
        s = red[threadIdx.x];
        #pragma unroll
        for (int o = 2; o > 0; o >>= 1) s += __shfl_xor_sync(0xfu, s, o);
        if (threadIdx.x == 0) *dstN = s;
    }
}

// ---------------------------------------------------------------------------
// Kernel 2: dual f16 mma GEMM (128x64 CTA, 8 warps 4x2, 32x32 warp tile)
//           + fused distance/exp/mix epilogue (f16, range-shifted) + psums
// ---------------------------------------------------------------------------
__global__ __launch_bounds__(256, 2) void fused_mma_kernel(
    const float* __restrict__ crP, const float* __restrict__ cfP)
{
    extern __shared__ char smem[];
    const uint32_t sb = smem_u32(smem);
    const int tid = threadIdx.x, wid = tid >> 5, l = tid & 31;
    const int wm = wid & 3, wn = wid >> 2;
    const int q0 = blockIdx.y * BM, c0 = blockIdx.x * BN;

    // --- loader mapping: 6 x 16B chunks per thread per stage ---
    const __half* gSrc[6]; uint32_t sDst[6];
    #pragma unroll
    for (int it = 0; it < 6; ++it) {
        const int id = tid + it * 256;            // 0..1535
        if (id < 1024) {
            const int mod = id >> 9, rem = id & 511;
            const int row = rem >> 2, c16 = rem & 3;
            gSrc[it] = g_h[2 + mod] + (size_t)(q0 + row) * Dn + c16 * 8;
            sDst[it] = (uint32_t)(mod * MOD_A + row * RSTRIDE + c16 * 16);
        } else {
            const int id2 = id - 1024;
            const int mod = id2 >> 8, rem = id2 & 255;
            const int row = rem >> 2, c16 = rem & 3;
            gSrc[it] = g_h[mod] + (size_t)(c0 + row) * Dn + c16 * 8;
            sDst[it] = (uint32_t)(BOFF + mod * MOD_B + row * RSTRIDE + c16 * 16);
        }
    }
    auto issue_stage = [&](int kc) {
        const uint32_t stg = sb + (uint32_t)(kc % STAGES) * STAGE_BYTES;
        const int ko = kc * KC;
        #pragma unroll
        for (int it = 0; it < 6; ++it)
            cp16(stg + sDst[it], gSrc[it] + ko);
        asm volatile("cp.async.commit_group;" ::: "memory");
    };

    // --- ldmatrix lane offsets (80B padded rows -> conflict-free) ---
    const uint32_t aOff = (uint32_t)(((l & 7) + ((l >> 3) & 1) * 8) * RSTRIDE
                                     + ((l >> 4) & 1) * 16);
    const uint32_t bOff4 = (uint32_t)(((l & 7) + ((l >> 4) & 1) * 8) * RSTRIDE
                                      + ((l >> 3) & 1) * 16);
    const uint32_t aBase = (uint32_t)(wm * 32 * RSTRIDE);
    const uint32_t bBase = (uint32_t)(BOFF + wn * 32 * RSTRIDE);

    float acc[2][2][4][4];   // [mod][m-frag(16)][n-frag(8)][e]
    #pragma unroll
    for (int m = 0; m < 2; ++m)
        #pragma unroll
        for (int i = 0; i < 2; ++i)
            #pragma unroll
            for (int j = 0; j < 4; ++j)
                #pragma unroll
                for (int e = 0; e < 4; ++e) acc[m][i][j][e] = 0.0f;

    issue_stage(0); issue_stage(1);

    for (int kc = 0; kc < NK; ++kc) {
        if (kc < NK - 1) asm volatile("cp.async.wait_group 1;" ::: "memory");
        else             asm volatile("cp.async.wait_group 0;" ::: "memory");
        __syncthreads();
        if (kc + 2 < NK) issue_stage(kc + 2);

        const uint32_t stg = sb + (uint32_t)(kc % STAGES) * STAGE_BYTES;
        #pragma unroll
        for (int s = 0; s < 2; ++s) {             // two k16 steps per KC=32
            #pragma unroll
            for (int m = 0; m < 2; ++m) {         // modality
                const uint32_t Am = stg + (uint32_t)(m * MOD_A) + aBase + s * 32 + aOff;
                const uint32_t Bm = stg + (uint32_t)(m * MOD_B) + bBase + s * 32 + bOff4;
                uint32_t a[2][4], b8[4][2];
                LDSM_X4(a[0][0], a[0][1], a[0][2], a[0][3], Am);
                LDSM_X4(a[1][0], a[1][1], a[1][2], a[1][3], Am + 16 * RSTRIDE);
                LDSM_X4(b8[0][0], b8[0][1], b8[1][0], b8[1][1], Bm);
                LDSM_X4(b8[2][0], b8[2][1], b8[3][0], b8[3][1], Bm + 16 * RSTRIDE);
                #pragma unroll
                for (int i = 0; i < 2; ++i)
                    #pragma unroll
                    for (int j = 0; j < 4; ++j)
                        MMA16816(acc[m][i][j], a[i], b8[j]);
            }
        }
    }

    // --- fused epilogue: o' = wr*e^{OFF-d1} + wf*e^{OFF-d2}, stored f16 ---
    const int r = l >> 2, cq = l & 3;
    const int psIdx = blockIdx.x * 2 + wn;
    #pragma unroll
    for (int i = 0; i < 2; ++i) {
        #pragma unroll
        for (int h = 0; h < 2; ++h) {
            const int q = q0 + wm * 32 + i * 16 + r + h * 8;
            const float ntR = g_nt[0][q], ntF = g_nt[1][q];
            const float rr = __ldg(crP + q), ff = __ldg(cfP + q);
            const float inv = 1.0f / (rr + ff);
            const float wr = rr * inv, wf = ff * inv;
            float rs = 0.0f;
            #pragma unroll
            for (int j = 0; j < 4; ++j) {
                const int c = c0 + wn * 32 + j * 8 + 2 * cq;
                float o[2];
                #pragma unroll
                for (int ec = 0; ec < 2; ++ec) {
                    const float sR = ntR + g_nc[0][c + ec] - 2.0f * acc[0][i][j][h * 2 + ec];
                    const float sF = ntF + g_nc[1][c + ec] - 2.0f * acc[1][i][j][h * 2 + ec];
                    const float d1 = sqrt_ap(fmaxf(sR, 0.0f));
                    const float d2 = sqrt_ap(fmaxf(sF, 0.0f));
                    o[ec] = wr * __expf(EXP_OFF - d1) + wf * __expf(EXP_OFF - d2);
                }
                rs += o[0] + o[1];
                *reinterpret_cast<__half2*>(g_o16 + (size_t)q * Cn + c) =
                    __floats2half2_rn(o[0], o[1]);
            }
            rs += __shfl_xor_sync(0xffffffffu, rs, 1);
            rs += __shfl_xor_sync(0xffffffffu, rs, 2);
            if (cq == 0) g_psum[psIdx][q] = rs;
        }
    }
}

// ---------------------------------------------------------------------------
// Kernel 3a: fold 128 partial sums per row -> g_inv (fixed order, deterministic)
// ---------------------------------------------------------------------------
__global__ __launch_bounds__(512) void rowsum_kernel()
{
    const int q = blockIdx.x * 512 + threadIdx.x;
    float s = 0.0f;
    #pragma unroll 8
    for (int c = 0; c < 2 * NCTA_C; ++c) s += g_psum[c][q];
    g_inv[q] = 1.0f / s;
}

// ---------------------------------------------------------------------------
// Kernel 3b: streaming scale f16 -> f32 out. Two rows per block (grid 2048),
// fully coalesced both sides, evict-first hints (data touched exactly once).
// ---------------------------------------------------------------------------
__global__ __launch_bounds__(256) void scale_kernel(float* __restrict__ out)
{
    const int q0 = blockIdx.x * 2;
    #pragma unroll
    for (int rr = 0; rr < 2; ++rr) {
        const int q = q0 + rr;
        const float inv = g_inv[q];
        const uint2* src = reinterpret_cast<const uint2*>(g_o16 + (size_t)q * Cn);
        float4* dst = reinterpret_cast<float4*>(out + (size_t)q * Cn);
        #pragma unroll
        for (int k = 0; k < 4; ++k) {
            const int j = threadIdx.x + k * 256;
            uint2 pk = __ldcs(src + j);
            const __half2 h0 = *reinterpret_cast<const __half2*>(&pk.x);
            const __half2 h1 = *reinterpret_cast<const __half2*>(&pk.y);
            const float2 a = __half22float2(h0);
            const float2 b = __half22float2(h1);
            __stcs(dst + j, make_float4(a.x * inv, a.y * inv, b.x * inv, b.y * inv));
        }
    }
}

// ---------------------------------------------------------------------------
// Entry point
// ---------------------------------------------------------------------------
extern "C" void kernel_launch(void* const* d_in, const int* in_sizes, int n_in,
                              void* d_out, int out_size)
{
    const float* c_rgb  = (const float*)d_in[0];
    const float* c_flow = (const float*)d_in[1];
    const float* t_rgb  = (const float*)d_in[2];
    const float* t_flow = (const float*)d_in[3];
    const float* cr     = (const float*)d_in[4];
    const float* cf     = (const float*)d_in[5];
    float* out = (float*)d_out;

    cudaFuncSetAttribute(fused_mma_kernel,
                         cudaFuncAttributeMaxDynamicSharedMemorySize, SMEM_TOTAL);

    prep_kernel<<<2 * (Qn + Cn), 128>>>(t_rgb, t_flow, c_rgb, c_flow);

    dim3 grid(NCTA_C, Qn / BM);   // (64, 32) = 2048 CTAs
    fused_mma_kernel<<<grid, 256, SMEM_TOTAL>>>(cr, cf);

    rowsum_kernel<<<Qn / 512, 512>>>();
    scale_kernel<<<Qn / 2, 256>>>(out);
}

// round 15
// speedup vs baseline: 1.4970x; 1.0049x over previous
#include <cuda_runtime.h>
#include <cuda_fp16.h>
#include <cstdint>

// Problem constants
constexpr int Qn = 4096, Cn = 4096, Dn = 1024;
#define EPSV 1e-6f
#define EXP_OFF 45.0f   // range shift: stored o' = e^{OFF}*o; divides out in normalize

// GEMM config: CTA 128(M) x 64(N), KC=32 halfs, 3-stage cp.async, 256 threads
// 8 warps as 4(m) x 2(n); warp tile 32x32. Occupancy 2.
constexpr int BM = 128, BN = 64, KC = 32;
constexpr int NK = Dn / KC;                 // 32
constexpr int STAGES = 3;
constexpr int RSTRIDE = 80;                 // bytes per 32-half row (64B data + 16B pad)
constexpr int MOD_A = 128 * RSTRIDE;        // 10240
constexpr int MOD_B = 64 * RSTRIDE;         // 5120
constexpr int BOFF = 2 * MOD_A;             // 20480
constexpr int STAGE_BYTES = 2 * MOD_A + 2 * MOD_B;  // 30720
constexpr int SMEM_TOTAL = STAGES * STAGE_BYTES;    // 92160 (x2 CTAs = 184320)
constexpr int NCTA_C = Cn / BN;             // 64 column tiles

// Scratch (static __device__ — no cudaMalloc allowed)
__device__ __half g_h[4][(size_t)Qn * Dn];  // 0=c_rgb 1=c_flow 2=t_rgb(+eps) 3=t_flow(+eps)
__device__ __half g_o16[(size_t)Qn * Cn];   // unnormalized posterior (range-shifted), f16
__device__ float g_nt[2][Qn];
__device__ float g_nc[2][Cn];
__device__ float g_psum[2 * NCTA_C][Qn];    // per-(colTile,warp-half) row partial sums
__device__ float g_inv[Qn];                 // 1 / rowsum (of shifted values)

// ---------------------------------------------------------------------------
// helpers
// ---------------------------------------------------------------------------
__device__ __forceinline__ uint32_t smem_u32(const void* p) {
    uint32_t a;
    asm("{ .reg .u64 t; cvta.to.shared.u64 t, %1; cvt.u32.u64 %0, t; }"
        : "=r"(a) : "l"(p));
    return a;
}
__device__ __forceinline__ void cp16(uint32_t saddr, const void* g) {
    asm volatile(
        "{ .reg .u64 gg; cvta.to.global.u64 gg, %1; "
        "cp.async.cg.shared.global [%0], [gg], 16; }"
        :: "r"(saddr), "l"(g));
}
__device__ __forceinline__ float sqrt_ap(float x) {
    float r; asm("sqrt.approx.f32 %0, %1;" : "=f"(r) : "f"(x)); return r;
}
#define LDSM_X4(r0, r1, r2, r3, addr) \
    asm volatile("ldmatrix.sync.aligned.m8n8.x4.shared.b16 {%0,%1,%2,%3}, [%4];" \
        : "=r"(r0), "=r"(r1), "=r"(r2), "=r"(r3) : "r"(addr))
#define MMA16816(d, a, b) \
    asm volatile( \
        "mma.sync.aligned.m16n8k16.row.col.f32.f16.f16.f32 " \
        "{%0,%1,%2,%3}, {%4,%5,%6,%7}, {%8,%9}, {%0,%1,%2,%3};" \
        : "+f"((d)[0]), "+f"((d)[1]), "+f"((d)[2]), "+f"((d)[3]) \
        : "r"((a)[0]), "r"((a)[1]), "r"((a)[2]), "r"((a)[3]), \
          "r"((b)[0]), "r"((b)[1]))

// ---------------------------------------------------------------------------
// Kernel 1: convert f32 -> f16 (rn, targets +eps first) + fp32 row norms.
// Input reads are single-touch -> streaming (__ldcs) to preserve L2 for g_h.
// ---------------------------------------------------------------------------
__global__ __launch_bounds__(128) void prep_kernel(
    const float* __restrict__ t_rgb, const float* __restrict__ t_flow,
    const float* __restrict__ c_rgb, const float* __restrict__ c_flow)
{
    int b = blockIdx.x;
    const float* src; float* dstN; __half* dstH; float eps;
    if (b < Qn)               { src = t_rgb  + (size_t)b * Dn;                 dstN = &g_nt[0][b];               dstH = g_h[2] + (size_t)b * Dn;                 eps = EPSV; }
    else if (b < 2 * Qn)      { src = t_flow + (size_t)(b - Qn) * Dn;          dstN = &g_nt[1][b - Qn];          dstH = g_h[3] + (size_t)(b - Qn) * Dn;          eps = EPSV; }
    else if (b < 2 * Qn + Cn) { src = c_rgb  + (size_t)(b - 2 * Qn) * Dn;      dstN = &g_nc[0][b - 2 * Qn];      dstH = g_h[0] + (size_t)(b - 2 * Qn) * Dn;      eps = 0.0f; }
    else                      { src = c_flow + (size_t)(b - 2 * Qn - Cn) * Dn; dstN = &g_nc[1][b - 2 * Qn - Cn]; dstH = g_h[1] + (size_t)(b - 2 * Qn - Cn) * Dn; eps = 0.0f; }

    float4 v0 = __ldcs(reinterpret_cast<const float4*>(src) + threadIdx.x);
    float4 v1 = __ldcs(reinterpret_cast<const float4*>(src) + threadIdx.x + 128);
    v0.x += eps; v0.y += eps; v0.z += eps; v0.w += eps;
    v1.x += eps; v1.y += eps; v1.z += eps; v1.w += eps;

    __half2* hp0 = reinterpret_cast<__half2*>(dstH) + threadIdx.x * 2;
    hp0[0] = __floats2half2_rn(v0.x, v0.y);
    hp0[1] = __floats2half2_rn(v0.z, v0.w);
    __half2* hp1 = reinterpret_cast<__half2*>(dstH) + (threadIdx.x + 128) * 2;
    hp1[0] = __floats2half2_rn(v1.x, v1.y);
    hp1[1] = __floats2half2_rn(v1.z, v1.w);

    float s = v0.x * v0.x + v0.y * v0.y + v0.z * v0.z + v0.w * v0.w
            + v1.x * v1.x + v1.y * v1.y + v1.z * v1.z + v1.w * v1.w;
    __shared__ float red[4];
    #pragma unroll
    for (int o = 16; o > 0; o >>= 1) s += __shfl_xor_sync(0xffffffffu, s, o);
    if ((threadIdx.x & 31) == 0) red[threadIdx.x >> 5] = s;
    __syncthreads();
    if (threadIdx.x < 4) {
        s = red[threadIdx.x];
        #pragma unroll
        for (int o = 2; o > 0; o >>= 1) s += __shfl_xor_sync(0xfu, s, o);
        if (threadIdx.x == 0) *dstN = s;
    }
}

// ---------------------------------------------------------------------------
// Kernel 2: dual f16 mma GEMM (128x64 CTA, 8 warps 4x2, 32x32 warp tile)
//           + fused distance/exp/mix epilogue (f16, range-shifted) + psums
// ---------------------------------------------------------------------------
__global__ __launch_bounds__(256, 2) void fused_mma_kernel(
    const float* __restrict__ crP, const float* __restrict__ cfP)
{
    extern __shared__ char smem[];
    const uint32_t sb = smem_u32(smem);
    const int tid = threadIdx.x, wid = tid >> 5, l = tid & 31;
    const int wm = wid & 3, wn = wid >> 2;
    const int q0 = blockIdx.y * BM, c0 = blockIdx.x * BN;

    // --- loader mapping: 6 x 16B chunks per thread per stage ---
    const __half* gSrc[6]; uint32_t sDst[6];
    #pragma unroll
    for (int it = 0; it < 6; ++it) {
        const int id = tid + it * 256;            // 0..1535
        if (id < 1024) {
            const int mod = id >> 9, rem = id & 511;
            const int row = rem >> 2, c16 = rem & 3;
            gSrc[it] = g_h[2 + mod] + (size_t)(q0 + row) * Dn + c16 * 8;
            sDst[it] = (uint32_t)(mod * MOD_A + row * RSTRIDE + c16 * 16);
        } else {
            const int id2 = id - 1024;
            const int mod = id2 >> 8, rem = id2 & 255;
            const int row = rem >> 2, c16 = rem & 3;
            gSrc[it] = g_h[mod] + (size_t)(c0 + row) * Dn + c16 * 8;
            sDst[it] = (uint32_t)(BOFF + mod * MOD_B + row * RSTRIDE + c16 * 16);
        }
    }
    auto issue_stage = [&](int kc) {
        const uint32_t stg = sb + (uint32_t)(kc % STAGES) * STAGE_BYTES;
        const int ko = kc * KC;
        #pragma unroll
        for (int it = 0; it < 6; ++it)
            cp16(stg + sDst[it], gSrc[it] + ko);
        asm volatile("cp.async.commit_group;" ::: "memory");
    };

    // --- ldmatrix lane offsets (80B padded rows -> conflict-free) ---
    const uint32_t aOff = (uint32_t)(((l & 7) + ((l >> 3) & 1) * 8) * RSTRIDE
                                     + ((l >> 4) & 1) * 16);
    const uint32_t bOff4 = (uint32_t)(((l & 7) + ((l >> 4) & 1) * 8) * RSTRIDE
                                      + ((l >> 3) & 1) * 16);
    const uint32_t aBase = (uint32_t)(wm * 32 * RSTRIDE);
    const uint32_t bBase = (uint32_t)(BOFF + wn * 32 * RSTRIDE);

    float acc[2][2][4][4];   // [mod][m-frag(16)][n-frag(8)][e]
    #pragma unroll
    for (int m = 0; m < 2; ++m)
        #pragma unroll
        for (int i = 0; i < 2; ++i)
            #pragma unroll
            for (int j = 0; j < 4; ++j)
                #pragma unroll
                for (int e = 0; e < 4; ++e) acc[m][i][j][e] = 0.0f;

    issue_stage(0); issue_stage(1);

    for (int kc = 0; kc < NK; ++kc) {
        if (kc < NK - 1) asm volatile("cp.async.wait_group 1;" ::: "memory");
        else             asm volatile("cp.async.wait_group 0;" ::: "memory");
        __syncthreads();
        if (kc + 2 < NK) issue_stage(kc + 2);

        const uint32_t stg = sb + (uint32_t)(kc % STAGES) * STAGE_BYTES;
        #pragma unroll
        for (int s = 0; s < 2; ++s) {             // two k16 steps per KC=32
            #pragma unroll
            for (int m = 0; m < 2; ++m) {         // modality
                const uint32_t Am = stg + (uint32_t)(m * MOD_A) + aBase + s * 32 + aOff;
                const uint32_t Bm = stg + (uint32_t)(m * MOD_B) + bBase + s * 32 + bOff4;
                uint32_t a[2][4], b8[4][2];
                LDSM_X4(a[0][0], a[0][1], a[0][2], a[0][3], Am);
                LDSM_X4(a[1][0], a[1][1], a[1][2], a[1][3], Am + 16 * RSTRIDE);
                LDSM_X4(b8[0][0], b8[0][1], b8[1][0], b8[1][1], Bm);
                LDSM_X4(b8[2][0], b8[2][1], b8[3][0], b8[3][1], Bm + 16 * RSTRIDE);
                #pragma unroll
                for (int i = 0; i < 2; ++i)
                    #pragma unroll
                    for (int j = 0; j < 4; ++j)
                        MMA16816(acc[m][i][j], a[i], b8[j]);
            }
        }
    }

    // --- fused epilogue: o' = wr*e^{OFF-d1} + wf*e^{OFF-d2}, stored f16 ---
    const int r = l >> 2, cq = l & 3;
    const int psIdx = blockIdx.x * 2 + wn;
    #pragma unroll
    for (int i = 0; i < 2; ++i) {
        #pragma unroll
        for (int h = 0; h < 2; ++h) {
            const int q = q0 + wm * 32 + i * 16 + r + h * 8;
            const float ntR = g_nt[0][q], ntF = g_nt[1][q];
            const float rr = __ldg(crP + q), ff = __ldg(cfP + q);
            const float inv = 1.0f / (rr + ff);
            const float wr = rr * inv, wf = ff * inv;
            float rs = 0.0f;
            #pragma unroll
            for (int j = 0; j < 4; ++j) {
                const int c = c0 + wn * 32 + j * 8 + 2 * cq;
                float o[2];
                #pragma unroll
                for (int ec = 0; ec < 2; ++ec) {
                    const float sR = ntR + g_nc[0][c + ec] - 2.0f * acc[0][i][j][h * 2 + ec];
                    const float sF = ntF + g_nc[1][c + ec] - 2.0f * acc[1][i][j][h * 2 + ec];
                    const float d1 = sqrt_ap(fmaxf(sR, 0.0f));
                    const float d2 = sqrt_ap(fmaxf(sF, 0.0f));
                    o[ec] = wr * __expf(EXP_OFF - d1) + wf * __expf(EXP_OFF - d2);
                }
                rs += o[0] + o[1];
                *reinterpret_cast<__half2*>(g_o16 + (size_t)q * Cn + c) =
                    __floats2half2_rn(o[0], o[1]);
            }
            rs += __shfl_xor_sync(0xffffffffu, rs, 1);
            rs += __shfl_xor_sync(0xffffffffu, rs, 2);
            if (cq == 0) g_psum[psIdx][q] = rs;
        }
    }
}

// ---------------------------------------------------------------------------
// Kernel 3a: fold 128 partial sums per row -> g_inv (fixed order, deterministic)
// ---------------------------------------------------------------------------
__global__ __launch_bounds__(512) void rowsum_kernel()
{
    const int q = blockIdx.x * 512 + threadIdx.x;
    float s = 0.0f;
    #pragma unroll 8
    for (int c = 0; c < 2 * NCTA_C; ++c) s += g_psum[c][q];
    g_inv[q] = 1.0f / s;
}

// ---------------------------------------------------------------------------
// Kernel 3b: streaming scale f16 -> f32 out. Four rows per block (grid 1024);
// g_inv loads hoisted, deep per-thread MLP, coalesced, single-touch hints.
// ---------------------------------------------------------------------------
__global__ __launch_bounds__(256) void scale_kernel(float* __restrict__ out)
{
    const int q0 = blockIdx.x * 4;

    float inv[4];
    #pragma unroll
    for (int rr = 0; rr < 4; ++rr) inv[rr] = g_inv[q0 + rr];

    #pragma unroll
    for (int rr = 0; rr < 4; ++rr) {
        const int q = q0 + rr;
        const uint2* src = reinterpret_cast<const uint2*>(g_o16 + (size_t)q * Cn);
        float4* dst = reinterpret_cast<float4*>(out + (size_t)q * Cn);

        uint2 pk[4];
        #pragma unroll
        for (int k = 0; k < 4; ++k)
            pk[k] = __ldcs(src + threadIdx.x + k * 256);
        #pragma unroll
        for (int k = 0; k < 4; ++k) {
            const __half2 h0 = *reinterpret_cast<const __half2*>(&pk[k].x);
            const __half2 h1 = *reinterpret_cast<const __half2*>(&pk[k].y);
            const float2 a = __half22float2(h0);
            const float2 b = __half22float2(h1);
            __stcs(dst + threadIdx.x + k * 256,
                   make_float4(a.x * inv[rr], a.y * inv[rr], b.x * inv[rr], b.y * inv[rr]));
        }
    }
}

// ---------------------------------------------------------------------------
// Entry point
// ---------------------------------------------------------------------------
extern "C" void kernel_launch(void* const* d_in, const int* in_sizes, int n_in,
                              void* d_out, int out_size)
{
    const float* c_rgb  = (const float*)d_in[0];
    const float* c_flow = (const float*)d_in[1];
    const float* t_rgb  = (const float*)d_in[2];
    const float* t_flow = (const float*)d_in[3];
    const float* cr     = (const float*)d_in[4];
    const float* cf     = (const float*)d_in[5];
    float* out = (float*)d_out;

    cudaFuncSetAttribute(fused_mma_kernel,
                         cudaFuncAttributeMaxDynamicSharedMemorySize, SMEM_TOTAL);

    prep_kernel<<<2 * (Qn + Cn), 128>>>(t_rgb, t_flow, c_rgb, c_flow);

    dim3 grid(NCTA_C, Qn / BM);   // (64, 32) = 2048 CTAs
    fused_mma_kernel<<<grid, 256, SMEM_TOTAL>>>(cr, cf);

    rowsum_kernel<<<Qn / 512, 512>>>();
    scale_kernel<<<Qn / 4, 256>>>(out);
}

// round 16
// speedup vs baseline: 1.5046x; 1.0050x over previous
#include <cuda_runtime.h>
#include <cuda_fp16.h>
#include <cstdint>

// Problem constants
constexpr int Qn = 4096, Cn = 4096, Dn = 1024;
#define EPSV 1e-6f
#define EXP_OFF 45.0f   // range shift: stored o' = e^{OFF}*o; divides out in normalize

// GEMM config: CTA 128(M) x 64(N), KC=32 halfs, 3-stage cp.async, 256 threads
// 8 warps as 4(m) x 2(n); warp tile 32x32. Occupancy 2.
constexpr int BM = 128, BN = 64, KC = 32;
constexpr int NK = Dn / KC;                 // 32
constexpr int STAGES = 3;
constexpr int RSTRIDE = 80;                 // bytes per 32-half row (64B data + 16B pad)
constexpr int MOD_A = 128 * RSTRIDE;        // 10240
constexpr int MOD_B = 64 * RSTRIDE;         // 5120
constexpr int BOFF = 2 * MOD_A;             // 20480
constexpr int STAGE_BYTES = 2 * MOD_A + 2 * MOD_B;  // 30720
constexpr int SMEM_TOTAL = STAGES * STAGE_BYTES;    // 92160 (x2 CTAs = 184320)
constexpr int NCTA_C = Cn / BN;             // 64 column tiles

// Scratch (static __device__ — no cudaMalloc allowed)
__device__ __half g_h[4][(size_t)Qn * Dn];  // 0=c_rgb 1=c_flow 2=t_rgb(+eps) 3=t_flow(+eps)
__device__ __half g_o16[(size_t)Qn * Cn];   // unnormalized posterior (range-shifted), f16
__device__ float g_nt[2][Qn];
__device__ float g_nc[2][Cn];
__device__ float g_psum[2 * NCTA_C][Qn];    // per-(colTile,warp-half) row partial sums
__device__ float g_inv[Qn];                 // 1 / rowsum (of shifted values)

// ---------------------------------------------------------------------------
// helpers
// ---------------------------------------------------------------------------
__device__ __forceinline__ uint32_t smem_u32(const void* p) {
    uint32_t a;
    asm("{ .reg .u64 t; cvta.to.shared.u64 t, %1; cvt.u32.u64 %0, t; }"
        : "=r"(a) : "l"(p));
    return a;
}
__device__ __forceinline__ void cp16(uint32_t saddr, const void* g) {
    asm volatile(
        "{ .reg .u64 gg; cvta.to.global.u64 gg, %1; "
        "cp.async.cg.shared.global [%0], [gg], 16; }"
        :: "r"(saddr), "l"(g));
}
__device__ __forceinline__ float sqrt_ap(float x) {
    float r; asm("sqrt.approx.f32 %0, %1;" : "=f"(r) : "f"(x)); return r;
}
#define LDSM_X4(r0, r1, r2, r3, addr) \
    asm volatile("ldmatrix.sync.aligned.m8n8.x4.shared.b16 {%0,%1,%2,%3}, [%4];" \
        : "=r"(r0), "=r"(r1), "=r"(r2), "=r"(r3) : "r"(addr))
#define MMA16816(d, a, b) \
    asm volatile( \
        "mma.sync.aligned.m16n8k16.row.col.f32.f16.f16.f32 " \
        "{%0,%1,%2,%3}, {%4,%5,%6,%7}, {%8,%9}, {%0,%1,%2,%3};" \
        : "+f"((d)[0]), "+f"((d)[1]), "+f"((d)[2]), "+f"((d)[3]) \
        : "r"((a)[0]), "r"((a)[1]), "r"((a)[2]), "r"((a)[3]), \
          "r"((b)[0]), "r"((b)[1]))

// ---------------------------------------------------------------------------
// Kernel 1: convert f32 -> f16 (rn, targets +eps first) + fp32 row norms.
// Input reads are single-touch -> streaming (__ldcs) to preserve L2 for g_h.
// ---------------------------------------------------------------------------
__global__ __launch_bounds__(128) void prep_kernel(
    const float* __restrict__ t_rgb, const float* __restrict__ t_flow,
    const float* __restrict__ c_rgb, const float* __restrict__ c_flow)
{
    int b = blockIdx.x;
    const float* src; float* dstN; __half* dstH; float eps;
    if (b < Qn)               { src = t_rgb  + (size_t)b * Dn;                 dstN = &g_nt[0][b];               dstH = g_h[2] + (size_t)b * Dn;                 eps = EPSV; }
    else if (b < 2 * Qn)      { src = t_flow + (size_t)(b - Qn) * Dn;          dstN = &g_nt[1][b - Qn];          dstH = g_h[3] + (size_t)(b - Qn) * Dn;          eps = EPSV; }
    else if (b < 2 * Qn + Cn) { src = c_rgb  + (size_t)(b - 2 * Qn) * Dn;      dstN = &g_nc[0][b - 2 * Qn];      dstH = g_h[0] + (size_t)(b - 2 * Qn) * Dn;      eps = 0.0f; }
    else                      { src = c_flow + (size_t)(b - 2 * Qn - Cn) * Dn; dstN = &g_nc[1][b - 2 * Qn - Cn]; dstH = g_h[1] + (size_t)(b - 2 * Qn - Cn) * Dn; eps = 0.0f; }

    float4 v0 = __ldcs(reinterpret_cast<const float4*>(src) + threadIdx.x);
    float4 v1 = __ldcs(reinterpret_cast<const float4*>(src) + threadIdx.x + 128);
    v0.x += eps; v0.y += eps; v0.z += eps; v0.w += eps;
    v1.x += eps; v1.y += eps; v1.z += eps; v1.w += eps;

    __half2* hp0 = reinterpret_cast<__half2*>(dstH) + threadIdx.x * 2;
    hp0[0] = __floats2half2_rn(v0.x, v0.y);
    hp0[1] = __floats2half2_rn(v0.z, v0.w);
    __half2* hp1 = reinterpret_cast<__half2*>(dstH) + (threadIdx.x + 128) * 2;
    hp1[0] = __floats2half2_rn(v1.x, v1.y);
    hp1[1] = __floats2half2_rn(v1.z, v1.w);

    float s = v0.x * v0.x + v0.y * v0.y + v0.z * v0.z + v0.w * v0.w
            + v1.x * v1.x + v1.y * v1.y + v1.z * v1.z + v1.w * v1.w;
    __shared__ float red[4];
    #pragma unroll
    for (int o = 16; o > 0; o >>= 1) s += __shfl_xor_sync(0xffffffffu, s, o);
    if ((threadIdx.x & 31) == 0) red[threadIdx.x >> 5] = s;
    __syncthreads();
    if (threadIdx.x < 4) {
        s = red[threadIdx.x];
        #pragma unroll
        for (int o = 2; o > 0; o >>= 1) s += __shfl_xor_sync(0xfu, s, o);
        if (threadIdx.x == 0) *dstN = s;
    }
}

// ---------------------------------------------------------------------------
// Kernel 2: dual f16 mma GEMM (128x64 CTA, 8 warps 4x2, 32x32 warp tile)
//           + fused distance/exp/mix epilogue (f16, range-shifted) + psums
// Mainloop order: sync -> issue(kc+2) -> wait(kc) -> compute. The sync already
// guarantees stage (kc-1)%3 (what kc+2 overwrites) is fully consumed, and
// wait_group 2 (3 chunks outstanding) still guarantees chunk kc is complete.
// ---------------------------------------------------------------------------
__global__ __launch_bounds__(256, 2) void fused_mma_kernel(
    const float* __restrict__ crP, const float* __restrict__ cfP)
{
    extern __shared__ char smem[];
    const uint32_t sb = smem_u32(smem);
    const int tid = threadIdx.x, wid = tid >> 5, l = tid & 31;
    const int wm = wid & 3, wn = wid >> 2;
    const int q0 = blockIdx.y * BM, c0 = blockIdx.x * BN;

    // --- loader mapping: 6 x 16B chunks per thread per stage ---
    const __half* gSrc[6]; uint32_t sDst[6];
    #pragma unroll
    for (int it = 0; it < 6; ++it) {
        const int id = tid + it * 256;            // 0..1535
        if (id < 1024) {
            const int mod = id >> 9, rem = id & 511;
            const int row = rem >> 2, c16 = rem & 3;
            gSrc[it] = g_h[2 + mod] + (size_t)(q0 + row) * Dn + c16 * 8;
            sDst[it] = (uint32_t)(mod * MOD_A + row * RSTRIDE + c16 * 16);
        } else {
            const int id2 = id - 1024;
            const int mod = id2 >> 8, rem = id2 & 255;
            const int row = rem >> 2, c16 = rem & 3;
            gSrc[it] = g_h[mod] + (size_t)(c0 + row) * Dn + c16 * 8;
            sDst[it] = (uint32_t)(BOFF + mod * MOD_B + row * RSTRIDE + c16 * 16);
        }
    }
    auto issue_stage = [&](int kc) {
        const uint32_t stg = sb + (uint32_t)(kc % STAGES) * STAGE_BYTES;
        const int ko = kc * KC;
        #pragma unroll
        for (int it = 0; it < 6; ++it)
            cp16(stg + sDst[it], gSrc[it] + ko);
        asm volatile("cp.async.commit_group;" ::: "memory");
    };

    // --- ldmatrix lane offsets (80B padded rows -> conflict-free) ---
    const uint32_t aOff = (uint32_t)(((l & 7) + ((l >> 3) & 1) * 8) * RSTRIDE
                                     + ((l >> 4) & 1) * 16);
    const uint32_t bOff4 = (uint32_t)(((l & 7) + ((l >> 4) & 1) * 8) * RSTRIDE
                                      + ((l >> 3) & 1) * 16);
    const uint32_t aBase = (uint32_t)(wm * 32 * RSTRIDE);
    const uint32_t bBase = (uint32_t)(BOFF + wn * 32 * RSTRIDE);

    float acc[2][2][4][4];   // [mod][m-frag(16)][n-frag(8)][e]
    #pragma unroll
    for (int m = 0; m < 2; ++m)
        #pragma unroll
        for (int i = 0; i < 2; ++i)
            #pragma unroll
            for (int j = 0; j < 4; ++j)
                #pragma unroll
                for (int e = 0; e < 4; ++e) acc[m][i][j][e] = 0.0f;

    issue_stage(0); issue_stage(1);

    for (int kc = 0; kc < NK; ++kc) {
        __syncthreads();
        if (kc + 2 < NK) {
            issue_stage(kc + 2);
            asm volatile("cp.async.wait_group 2;" ::: "memory");
        } else if (kc + 1 < NK) {
            asm volatile("cp.async.wait_group 1;" ::: "memory");
        } else {
            asm volatile("cp.async.wait_group 0;" ::: "memory");
        }

        const uint32_t stg = sb + (uint32_t)(kc % STAGES) * STAGE_BYTES;
        #pragma unroll
        for (int s = 0; s < 2; ++s) {             // two k16 steps per KC=32
            #pragma unroll
            for (int m = 0; m < 2; ++m) {         // modality
                const uint32_t Am = stg + (uint32_t)(m * MOD_A) + aBase + s * 32 + aOff;
                const uint32_t Bm = stg + (uint32_t)(m * MOD_B) + bBase + s * 32 + bOff4;
                uint32_t a[2][4], b8[4][2];
                LDSM_X4(a[0][0], a[0][1], a[0][2], a[0][3], Am);
                LDSM_X4(a[1][0], a[1][1], a[1][2], a[1][3], Am + 16 * RSTRIDE);
                LDSM_X4(b8[0][0], b8[0][1], b8[1][0], b8[1][1], Bm);
                LDSM_X4(b8[2][0], b8[2][1], b8[3][0], b8[3][1], Bm + 16 * RSTRIDE);
                #pragma unroll
                for (int i = 0; i < 2; ++i)
                    #pragma unroll
                    for (int j = 0; j < 4; ++j)
                        MMA16816(acc[m][i][j], a[i], b8[j]);
            }
        }
    }

    // --- fused epilogue: o' = wr*e^{OFF-d1} + wf*e^{OFF-d2}, stored f16 ---
    const int r = l >> 2, cq = l & 3;
    const int psIdx = blockIdx.x * 2 + wn;
    #pragma unroll
    for (int i = 0; i < 2; ++i) {
        #pragma unroll
        for (int h = 0; h < 2; ++h) {
            const int q = q0 + wm * 32 + i * 16 + r + h * 8;
            const float ntR = g_nt[0][q], ntF = g_nt[1][q];
            const float rr = __ldg(crP + q), ff = __ldg(cfP + q);
            const float inv = 1.0f / (rr + ff);
            const float wr = rr * inv, wf = ff * inv;
            float rs = 0.0f;
            #pragma unroll
            for (int j = 0; j < 4; ++j) {
                const int c = c0 + wn * 32 + j * 8 + 2 * cq;
                float o[2];
                #pragma unroll
                for (int ec = 0; ec < 2; ++ec) {
                    const float sR = ntR + g_nc[0][c + ec] - 2.0f * acc[0][i][j][h * 2 + ec];
                    const float sF = ntF + g_nc[1][c + ec] - 2.0f * acc[1][i][j][h * 2 + ec];
                    const float d1 = sqrt_ap(fmaxf(sR, 0.0f));
                    const float d2 = sqrt_ap(fmaxf(sF, 0.0f));
                    o[ec] = wr * __expf(EXP_OFF - d1) + wf * __expf(EXP_OFF - d2);
                }
                rs += o[0] + o[1];
                *reinterpret_cast<__half2*>(g_o16 + (size_t)q * Cn + c) =
                    __floats2half2_rn(o[0], o[1]);
            }
            rs += __shfl_xor_sync(0xffffffffu, rs, 1);
            rs += __shfl_xor_sync(0xffffffffu, rs, 2);
            if (cq == 0) g_psum[psIdx][q] = rs;
        }
    }
}

// ---------------------------------------------------------------------------
// Kernel 3a: fold 128 partial sums per row -> g_inv (fixed order, deterministic)
// ---------------------------------------------------------------------------
__global__ __launch_bounds__(512) void rowsum_kernel()
{
    const int q = blockIdx.x * 512 + threadIdx.x;
    float s = 0.0f;
    #pragma unroll 8
    for (int c = 0; c < 2 * NCTA_C; ++c) s += __ldcs(&g_psum[c][q]);
    g_inv[q] = 1.0f / s;
}

// ---------------------------------------------------------------------------
// Kernel 3b: streaming scale f16 -> f32 out. Four rows per block (grid 1024);
// g_inv loads hoisted, deep per-thread MLP, coalesced, single-touch hints.
// ---------------------------------------------------------------------------
__global__ __launch_bounds__(256) void scale_kernel(float* __restrict__ out)
{
    const int q0 = blockIdx.x * 4;

    float inv[4];
    #pragma unroll
    for (int rr = 0; rr < 4; ++rr) inv[rr] = g_inv[q0 + rr];

    #pragma unroll
    for (int rr = 0; rr < 4; ++rr) {
        const int q = q0 + rr;
        const uint2* src = reinterpret_cast<const uint2*>(g_o16 + (size_t)q * Cn);
        float4* dst = reinterpret_cast<float4*>(out + (size_t)q * Cn);

        uint2 pk[4];
        #pragma unroll
        for (int k = 0; k < 4; ++k)
            pk[k] = __ldcs(src + threadIdx.x + k * 256);
        #pragma unroll
        for (int k = 0; k < 4; ++k) {
            const __half2 h0 = *reinterpret_cast<const __half2*>(&pk[k].x);
            const __half2 h1 = *reinterpret_cast<const __half2*>(&pk[k].y);
            const float2 a = __half22float2(h0);
            const float2 b = __half22float2(h1);
            __stcs(dst + threadIdx.x + k * 256,
                   make_float4(a.x * inv[rr], a.y * inv[rr], b.x * inv[rr], b.y * inv[rr]));
        }
    }
}

// ---------------------------------------------------------------------------
// Entry point
// ---------------------------------------------------------------------------
extern "C" void kernel_launch(void* const* d_in, const int* in_sizes, int n_in,
                              void* d_out, int out_size)
{
    const float* c_rgb  = (const float*)d_in[0];
    const float* c_flow = (const float*)d_in[1];
    const float* t_rgb  = (const float*)d_in[2];
    const float* t_flow = (const float*)d_in[3];
    const float* cr     = (const float*)d_in[4];
    const float* cf     = (const float*)d_in[5];
    float* out = (float*)d_out;

    cudaFuncSetAttribute(fused_mma_kernel,
                         cudaFuncAttributeMaxDynamicSharedMemorySize, SMEM_TOTAL);

    prep_kernel<<<2 * (Qn + Cn), 128>>>(t_rgb, t_flow, c_rgb, c_flow);

    dim3 grid(NCTA_C, Qn / BM);   // (64, 32) = 2048 CTAs
    fused_mma_kernel<<<grid, 256, SMEM_TOTAL>>>(cr, cf);

    rowsum_kernel<<<Qn / 512, 512>>>();
    scale_kernel<<<Qn / 4, 256>>>(out);
}

// round 17
// speedup vs baseline: 1.5342x; 1.0197x over previous
#include <cuda_runtime.h>
#include <cuda_fp16.h>
#include <cstdint>

// Problem constants
constexpr int Qn = 4096, Cn = 4096, Dn = 1024;
#define EPSV 1e-6f
#define EXP_OFF 45.0f   // range shift: stored o' = e^{OFF}*o; divides out in normalize

// GEMM config: CTA 128(M) x 64(N), KC=32 halfs, 3-stage cp.async, 256 threads
// 8 warps as 4(m) x 2(n); warp tile 32x32. Occupancy 2.
constexpr int BM = 128, BN = 64, KC = 32;
constexpr int NK = Dn / KC;                 // 32
constexpr int STAGES = 3;
constexpr int RSTRIDE = 80;                 // bytes per 32-half row (64B data + 16B pad)
constexpr int MOD_A = 128 * RSTRIDE;        // 10240
constexpr int MOD_B = 64 * RSTRIDE;         // 5120
constexpr int BOFF = 2 * MOD_A;             // 20480
constexpr int STAGE_BYTES = 2 * MOD_A + 2 * MOD_B;  // 30720
constexpr int SMEM_TOTAL = STAGES * STAGE_BYTES;    // 92160 (x2 CTAs = 184320)
constexpr int NCTA_C = Cn / BN;             // 64 column tiles
constexpr int NPSUM = 2 * NCTA_C;           // 128 partials per row

// Scratch (static __device__ — no cudaMalloc allowed)
__device__ __half g_h[4][(size_t)Qn * Dn];  // 0=c_rgb 1=c_flow 2=t_rgb(+eps) 3=t_flow(+eps)
__device__ __half g_o16[(size_t)Qn * Cn];   // unnormalized posterior (range-shifted), f16
__device__ float g_nt[2][Qn];
__device__ float g_nc[2][Cn];
__device__ float g_psum[NPSUM][Qn];         // per-(colTile,warp-half) row partial sums

// ---------------------------------------------------------------------------
// helpers
// ---------------------------------------------------------------------------
__device__ __forceinline__ uint32_t smem_u32(const void* p) {
    uint32_t a;
    asm("{ .reg .u64 t; cvta.to.shared.u64 t, %1; cvt.u32.u64 %0, t; }"
        : "=r"(a) : "l"(p));
    return a;
}
__device__ __forceinline__ void cp16(uint32_t saddr, const void* g) {
    asm volatile(
        "{ .reg .u64 gg; cvta.to.global.u64 gg, %1; "
        "cp.async.cg.shared.global [%0], [gg], 16; }"
        :: "r"(saddr), "l"(g));
}
__device__ __forceinline__ float sqrt_ap(float x) {
    float r; asm("sqrt.approx.f32 %0, %1;" : "=f"(r) : "f"(x)); return r;
}
#define LDSM_X4(r0, r1, r2, r3, addr) \
    asm volatile("ldmatrix.sync.aligned.m8n8.x4.shared.b16 {%0,%1,%2,%3}, [%4];" \
        : "=r"(r0), "=r"(r1), "=r"(r2), "=r"(r3) : "r"(addr))
#define MMA16816(d, a, b) \
    asm volatile( \
        "mma.sync.aligned.m16n8k16.row.col.f32.f16.f16.f32 " \
        "{%0,%1,%2,%3}, {%4,%5,%6,%7}, {%8,%9}, {%0,%1,%2,%3};" \
        : "+f"((d)[0]), "+f"((d)[1]), "+f"((d)[2]), "+f"((d)[3]) \
        : "r"((a)[0]), "r"((a)[1]), "r"((a)[2]), "r"((a)[3]), \
          "r"((b)[0]), "r"((b)[1]))

// ---------------------------------------------------------------------------
// Kernel 1: convert f32 -> f16 (rn, targets +eps first) + fp32 row norms.
// Input reads are single-touch -> streaming (__ldcs) to preserve L2 for g_h.
// ---------------------------------------------------------------------------
__global__ __launch_bounds__(128) void prep_kernel(
    const float* __restrict__ t_rgb, const float* __restrict__ t_flow,
    const float* __restrict__ c_rgb, const float* __restrict__ c_flow)
{
    int b = blockIdx.x;
    const float* src; float* dstN; __half* dstH; float eps;
    if (b < Qn)               { src = t_rgb  + (size_t)b * Dn;                 dstN = &g_nt[0][b];               dstH = g_h[2] + (size_t)b * Dn;                 eps = EPSV; }
    else if (b < 2 * Qn)      { src = t_flow + (size_t)(b - Qn) * Dn;          dstN = &g_nt[1][b - Qn];          dstH = g_h[3] + (size_t)(b - Qn) * Dn;          eps = EPSV; }
    else if (b < 2 * Qn + Cn) { src = c_rgb  + (size_t)(b - 2 * Qn) * Dn;      dstN = &g_nc[0][b - 2 * Qn];      dstH = g_h[0] + (size_t)(b - 2 * Qn) * Dn;      eps = 0.0f; }
    else                      { src = c_flow + (size_t)(b - 2 * Qn - Cn) * Dn; dstN = &g_nc[1][b - 2 * Qn - Cn]; dstH = g_h[1] + (size_t)(b - 2 * Qn - Cn) * Dn; eps = 0.0f; }

    float4 v0 = __ldcs(reinterpret_cast<const float4*>(src) + threadIdx.x);
    float4 v1 = __ldcs(reinterpret_cast<const float4*>(src) + threadIdx.x + 128);
    v0.x += eps; v0.y += eps; v0.z += eps; v0.w += eps;
    v1.x += eps; v1.y += eps; v1.z += eps; v1.w += eps;

    __half2* hp0 = reinterpret_cast<__half2*>(dstH) + threadIdx.x * 2;
    hp0[0] = __floats2half2_rn(v0.x, v0.y);
    hp0[1] = __floats2half2_rn(v0.z, v0.w);
    __half2* hp1 = reinterpret_cast<__half2*>(dstH) + (threadIdx.x + 128) * 2;
    hp1[0] = __floats2half2_rn(v1.x, v1.y);
    hp1[1] = __floats2half2_rn(v1.z, v1.w);

    float s = v0.x * v0.x + v0.y * v0.y + v0.z * v0.z + v0.w * v0.w
            + v1.x * v1.x + v1.y * v1.y + v1.z * v1.z + v1.w * v1.w;
    __shared__ float red[4];
    #pragma unroll
    for (int o = 16; o > 0; o >>= 1) s += __shfl_xor_sync(0xffffffffu, s, o);
    if ((threadIdx.x & 31) == 0) red[threadIdx.x >> 5] = s;
    __syncthreads();
    if (threadIdx.x < 4) {
        s = red[threadIdx.x];
        #pragma unroll
        for (int o = 2; o > 0; o >>= 1) s += __shfl_xor_sync(0xfu, s, o);
        if (threadIdx.x == 0) *dstN = s;
    }
}

// ---------------------------------------------------------------------------
// Kernel 2: dual f16 mma GEMM (128x64 CTA, 8 warps 4x2, 32x32 warp tile)
//           + fused distance/exp/mix epilogue (f16, range-shifted) + psums
// Mainloop order: sync -> issue(kc+2) -> wait(kc) -> compute. The sync already
// guarantees stage (kc-1)%3 (what kc+2 overwrites) is fully consumed, and
// wait_group 2 (3 chunks outstanding) still guarantees chunk kc is complete.
// ---------------------------------------------------------------------------
__global__ __launch_bounds__(256, 2) void fused_mma_kernel(
    const float* __restrict__ crP, const float* __restrict__ cfP)
{
    extern __shared__ char smem[];
    const uint32_t sb = smem_u32(smem);
    const int tid = threadIdx.x, wid = tid >> 5, l = tid & 31;
    const int wm = wid & 3, wn = wid >> 2;
    const int q0 = blockIdx.y * BM, c0 = blockIdx.x * BN;

    // --- loader mapping: 6 x 16B chunks per thread per stage ---
    const __half* gSrc[6]; uint32_t sDst[6];
    #pragma unroll
    for (int it = 0; it < 6; ++it) {
        const int id = tid + it * 256;            // 0..1535
        if (id < 1024) {
            const int mod = id >> 9, rem = id & 511;
            const int row = rem >> 2, c16 = rem & 3;
            gSrc[it] = g_h[2 + mod] + (size_t)(q0 + row) * Dn + c16 * 8;
            sDst[it] = (uint32_t)(mod * MOD_A + row * RSTRIDE + c16 * 16);
        } else {
            const int id2 = id - 1024;
            const int mod = id2 >> 8, rem = id2 & 255;
            const int row = rem >> 2, c16 = rem & 3;
            gSrc[it] = g_h[mod] + (size_t)(c0 + row) * Dn + c16 * 8;
            sDst[it] = (uint32_t)(BOFF + mod * MOD_B + row * RSTRIDE + c16 * 16);
        }
    }
    auto issue_stage = [&](int kc) {
        const uint32_t stg = sb + (uint32_t)(kc % STAGES) * STAGE_BYTES;
        const int ko = kc * KC;
        #pragma unroll
        for (int it = 0; it < 6; ++it)
            cp16(stg + sDst[it], gSrc[it] + ko);
        asm volatile("cp.async.commit_group;" ::: "memory");
    };

    // --- ldmatrix lane offsets (80B padded rows -> conflict-free) ---
    const uint32_t aOff = (uint32_t)(((l & 7) + ((l >> 3) & 1) * 8) * RSTRIDE
                                     + ((l >> 4) & 1) * 16);
    const uint32_t bOff4 = (uint32_t)(((l & 7) + ((l >> 4) & 1) * 8) * RSTRIDE
                                      + ((l >> 3) & 1) * 16);
    const uint32_t aBase = (uint32_t)(wm * 32 * RSTRIDE);
    const uint32_t bBase = (uint32_t)(BOFF + wn * 32 * RSTRIDE);

    float acc[2][2][4][4];   // [mod][m-frag(16)][n-frag(8)][e]
    #pragma unroll
    for (int m = 0; m < 2; ++m)
        #pragma unroll
        for (int i = 0; i < 2; ++i)
            #pragma unroll
            for (int j = 0; j < 4; ++j)
                #pragma unroll
                for (int e = 0; e < 4; ++e) acc[m][i][j][e] = 0.0f;

    issue_stage(0); issue_stage(1);

    for (int kc = 0; kc < NK; ++kc) {
        __syncthreads();
        if (kc + 2 < NK) {
            issue_stage(kc + 2);
            asm volatile("cp.async.wait_group 2;" ::: "memory");
        } else if (kc + 1 < NK) {
            asm volatile("cp.async.wait_group 1;" ::: "memory");
        } else {
            asm volatile("cp.async.wait_group 0;" ::: "memory");
        }

        const uint32_t stg = sb + (uint32_t)(kc % STAGES) * STAGE_BYTES;
        #pragma unroll
        for (int s = 0; s < 2; ++s) {             // two k16 steps per KC=32
            #pragma unroll
            for (int m = 0; m < 2; ++m) {         // modality
                const uint32_t Am = stg + (uint32_t)(m * MOD_A) + aBase + s * 32 + aOff;
                const uint32_t Bm = stg + (uint32_t)(m * MOD_B) + bBase + s * 32 + bOff4;
                uint32_t a[2][4], b8[4][2];
                LDSM_X4(a[0][0], a[0][1], a[0][2], a[0][3], Am);
                LDSM_X4(a[1][0], a[1][1], a[1][2], a[1][3], Am + 16 * RSTRIDE);
                LDSM_X4(b8[0][0], b8[0][1], b8[1][0], b8[1][1], Bm);
                LDSM_X4(b8[2][0], b8[2][1], b8[3][0], b8[3][1], Bm + 16 * RSTRIDE);
                #pragma unroll
                for (int i = 0; i < 2; ++i)
                    #pragma unroll
                    for (int j = 0; j < 4; ++j)
                        MMA16816(acc[m][i][j], a[i], b8[j]);
            }
        }
    }

    // --- fused epilogue: o' = wr*e^{OFF-d1} + wf*e^{OFF-d2}, stored f16 ---
    const int r = l >> 2, cq = l & 3;
    const int psIdx = blockIdx.x * 2 + wn;
    #pragma unroll
    for (int i = 0; i < 2; ++i) {
        #pragma unroll
        for (int h = 0; h < 2; ++h) {
            const int q = q0 + wm * 32 + i * 16 + r + h * 8;
            const float ntR = g_nt[0][q], ntF = g_nt[1][q];
            const float rr = __ldg(crP + q), ff = __ldg(cfP + q);
            const float inv = 1.0f / (rr + ff);
            const float wr = rr * inv, wf = ff * inv;
            float rs = 0.0f;
            #pragma unroll
            for (int j = 0; j < 4; ++j) {
                const int c = c0 + wn * 32 + j * 8 + 2 * cq;
                float o[2];
                #pragma unroll
                for (int ec = 0; ec < 2; ++ec) {
                    const float sR = ntR + g_nc[0][c + ec] - 2.0f * acc[0][i][j][h * 2 + ec];
                    const float sF = ntF + g_nc[1][c + ec] - 2.0f * acc[1][i][j][h * 2 + ec];
                    const float d1 = sqrt_ap(fmaxf(sR, 0.0f));
                    const float d2 = sqrt_ap(fmaxf(sF, 0.0f));
                    o[ec] = wr * __expf(EXP_OFF - d1) + wf * __expf(EXP_OFF - d2);
                }
                rs += o[0] + o[1];
                *reinterpret_cast<__half2*>(g_o16 + (size_t)q * Cn + c) =
                    __floats2half2_rn(o[0], o[1]);
            }
            rs += __shfl_xor_sync(0xffffffffu, rs, 1);
            rs += __shfl_xor_sync(0xffffffffu, rs, 2);
            if (cq == 0) g_psum[psIdx][q] = rs;
        }
    }
}

// ---------------------------------------------------------------------------
// Kernel 3: fused rowsum + streaming scale. Four rows per block (grid 1024).
// All threads issue their 16 streaming row loads FIRST (long-latency, fills
// the L1tex queue); warps 0-3 then each fold one row's 128 psums (4 loads per
// lane, fixed order -> deterministic) while those loads are in flight; one
// barrier; convert + evict-first store.
// ---------------------------------------------------------------------------
__global__ __launch_bounds__(256) void scale_kernel(float* __restrict__ out)
{
    const int q0 = blockIdx.x * 4;
    const int wid = threadIdx.x >> 5, lane = threadIdx.x & 31;
    __shared__ float sinv[4];

    // Phase 1: issue all row loads (streaming; touched exactly once)
    uint2 pk[4][4];
    #pragma unroll
    for (int rr = 0; rr < 4; ++rr) {
        const uint2* src = reinterpret_cast<const uint2*>(g_o16 + (size_t)(q0 + rr) * Cn);
        #pragma unroll
        for (int k = 0; k < 4; ++k)
            pk[rr][k] = __ldcs(src + threadIdx.x + k * 256);
    }

    // Phase 2: warps 0-3 reduce their row's psums (overlaps phase-1 latency)
    if (wid < 4) {
        const int q = q0 + wid;
        float s = g_psum[lane][q] + g_psum[lane + 32][q]
                + g_psum[lane + 64][q] + g_psum[lane + 96][q];
        #pragma unroll
        for (int o = 16; o > 0; o >>= 1) s += __shfl_xor_sync(0xffffffffu, s, o);
        if (lane == 0) sinv[wid] = 1.0f / s;
    }
    __syncthreads();

    // Phase 3: convert + scale + store
    #pragma unroll
    for (int rr = 0; rr < 4; ++rr) {
        const float inv = sinv[rr];
        float4* dst = reinterpret_cast<float4*>(out + (size_t)(q0 + rr) * Cn);
        #pragma unroll
        for (int k = 0; k < 4; ++k) {
            const __half2 h0 = *reinterpret_cast<const __half2*>(&pk[rr][k].x);
            const __half2 h1 = *reinterpret_cast<const __half2*>(&pk[rr][k].y);
            const float2 a = __half22float2(h0);
            const float2 b = __half22float2(h1);
            __stcs(dst + threadIdx.x + k * 256,
                   make_float4(a.x * inv, a.y * inv, b.x * inv, b.y * inv));
        }
    }
}

// ---------------------------------------------------------------------------
// Entry point
// ---------------------------------------------------------------------------
extern "C" void kernel_launch(void* const* d_in, const int* in_sizes, int n_in,
                              void* d_out, int out_size)
{
    const float* c_rgb  = (const float*)d_in[0];
    const float* c_flow = (const float*)d_in[1];
    const float* t_rgb  = (const float*)d_in[2];
    const float* t_flow = (const float*)d_in[3];
    const float* cr     = (const float*)d_in[4];
    const float* cf     = (const float*)d_in[5];
    float* out = (float*)d_out;

    cudaFuncSetAttribute(fused_mma_kernel,
                         cudaFuncAttributeMaxDynamicSharedMemorySize, SMEM_TOTAL);

    prep_kernel<<<2 * (Qn + Cn), 128>>>(t_rgb, t_flow, c_rgb, c_flow);

    dim3 grid(NCTA_C, Qn / BM);   // (64, 32) = 2048 CTAs
    fused_mma_kernel<<<grid, 256, SMEM_TOTAL>>>(cr, cf);

    scale_kernel<<<Qn / 4, 256>>>(out);
}